// round 11
// baseline (speedup 1.0000x reference)
#include <cuda_runtime.h>
#include <math.h>

#define BG     64
#define NG     1000
#define NTOT   64000
#define KNN    10
#define NLAYER 4
#define EMB    128
#define EALL   (NTOT*KNN)   /* 640000 */

typedef unsigned long long u64;

// ----------------------------- scratch (device globals) -----------------------------
__device__ float g_h   [NTOT*EMB];
__device__ float g_h2  [NTOT*EMB];
__device__ float g_magg[NTOT*EMB];
__device__ float g_p1  [NTOT*EMB];          // h @ Wm1 + bm (dst)
__device__ float g_p2  [NTOT*EMB];          // h @ Wm2      (src)
__device__ float g_posA[NTOT*2];
__device__ float g_posB[NTOT*2];
__device__ int   g_src [EALL];
__device__ int   g_rowptr[NTOT+1];
__device__ int   g_cnt [NTOT];
__device__ int   g_fill[NTOT];
__device__ int   g_perm[EALL];
__device__ float g_colsum[EMB];
__device__ float g_sumsq;
__device__ float g_mu[EMB];
__device__ float g_inv;

// ----------------------------- packed f32x2 helpers --------------------------------
__device__ __forceinline__ u64 pk2(float v){
    u64 r;
    asm("mov.b64 %0, {%1, %1};" : "=l"(r) : "f"(v));
    return r;
}
__device__ __forceinline__ void fma2(u64& d, u64 a, u64 b){
    asm("fma.rn.f32x2 %0, %1, %2, %3;" : "=l"(d) : "l"(a), "l"(b), "l"(d));
}
__device__ __forceinline__ void unpk2(float& lo, float& hi, u64 v){
    asm("mov.b64 {%0, %1}, %2;" : "=f"(lo), "=f"(hi) : "l"(v));
}

// ----------------------------- init: embed + pos copy + csr zero -------------------
__global__ void k_init(const float* __restrict__ hf, const float* __restrict__ We,
                       const float* __restrict__ be, const float* __restrict__ pos)
{
    int idx = blockIdx.x*blockDim.x + threadIdx.x;
    if (idx < NTOT*2) g_posA[idx] = pos[idx];
    if (idx < NTOT)   { g_cnt[idx] = 0; g_fill[idx] = 0; }
    if (idx >= NTOT*EMB) return;
    int n = idx >> 7, c = idx & 127;
    float s = be[c];
    #pragma unroll
    for (int k = 0; k < 5; k++) s += hf[n*5+k] * We[k*EMB+c];
    g_h[idx] = fmaxf(s, 0.f);
}

// ----------------------------- layer-0 CSR build -----------------------------------
__global__ void k_count(const int* __restrict__ dst)
{
    int e = blockIdx.x*blockDim.x + threadIdx.x;
    if (e < EALL) atomicAdd(&g_cnt[dst[e]], 1);
}
__global__ void k_scan()   // 1 block, 1024 threads
{
    __shared__ int part[1024];
    const int CH = 63;
    int t = threadIdx.x;
    int beg = t*CH, end = min(beg + CH, NTOT);
    int s = 0;
    for (int i = beg; i < end; i++) s += g_cnt[i];
    part[t] = s;
    __syncthreads();
    if (t == 0) {
        int run = 0;
        for (int i = 0; i < 1024; i++) { int v = part[i]; part[i] = run; run += v; }
    }
    __syncthreads();
    int run = part[t];
    for (int i = beg; i < end; i++) { g_rowptr[i] = run; run += g_cnt[i]; }
    if (t == 0) g_rowptr[NTOT] = EALL;
}
__global__ void k_fill(const int* __restrict__ dst)
{
    int e = blockIdx.x*blockDim.x + threadIdx.x;
    if (e >= EALL) return;
    int d = dst[e];
    int o = atomicAdd(&g_fill[d], 1);
    g_perm[g_rowptr[d] + o] = e;
}

// ----------------------------- kNN (warp per center node) --------------------------
__global__ void k_knn(const float* __restrict__ pos)
{
    __shared__ float2 sp[NG];
    int g  = blockIdx.x / (NG/4);
    int nb = blockIdx.x % (NG/4);
    for (int i = threadIdx.x; i < NG; i += 128)
        sp[i] = ((const float2*)pos)[g*NG + i];
    __syncthreads();
    int w = threadIdx.x >> 5, lane = threadIdx.x & 31;
    int i = nb*4 + w;
    float2 pi = sp[i];
    float bd[KNN]; int bj[KNN];
    #pragma unroll
    for (int r = 0; r < KNN; r++) { bd[r] = 3.4e38f; bj[r] = 0x7fffffff; }
    for (int j = lane; j < NG; j += 32) {
        if (j == i) continue;
        float dx = pi.x - sp[j].x, dy = pi.y - sp[j].y;
        float d2 = dx*dx + dy*dy;
        if (d2 < bd[KNN-1] || (d2 == bd[KNN-1] && j < bj[KNN-1])) {
            int r = KNN-1;
            while (r > 0 && (d2 < bd[r-1] || (d2 == bd[r-1] && j < bj[r-1]))) {
                bd[r] = bd[r-1]; bj[r] = bj[r-1]; r--;
            }
            bd[r] = d2; bj[r] = j;
        }
    }
    int head = 0;
    int base = (g*NG + i)*KNN;
    for (int r = 0; r < KNN; r++) {
        float d = (head < KNN) ? bd[head] : 3.4e38f;
        int   j = (head < KNN) ? bj[head] : 0x7fffffff;
        float dm = d; int jm = j;
        #pragma unroll
        for (int off = 16; off >= 1; off >>= 1) {
            float od = __shfl_xor_sync(0xffffffffu, dm, off);
            int   oj = __shfl_xor_sync(0xffffffffu, jm, off);
            if (od < dm || (od == dm && oj < jm)) { dm = od; jm = oj; }
        }
        if (jm == j && dm == d && head < KNN) head++;
        if (lane == 0) g_src[base + r] = g*NG + jm;
    }
}

// ----------------------------- node GEMM: P1/P2 (128x128 tile, f32x2) --------------
// grid 1000: bid<500 -> P1 = h@Wm[0:128] + bm ; else -> P2 = h@Wm[128:256]
__global__ __launch_bounds__(256) void k_pgemm(
    const float* __restrict__ Wm, const float* __restrict__ bm)
{
    __shared__ __align__(16) float Xs[2][8][132];
    __shared__ __align__(16) float Ws[2][8][128];

    int t = threadIdx.x;
    int half = blockIdx.x >= 500;
    int n0 = (blockIdx.x - half*500) * 128;
    const float* W = Wm + (half ? EMB*EMB : 0);
    float* C = half ? g_p2 : g_p1;

    if (blockIdx.x == 0) {
        if (t < 128) g_colsum[t] = 0.f;
        if (t == 0)  g_sumsq = 0.f;
    }

    int xr = t >> 1, xq = (t & 1) * 4;
    int wk = t >> 5, wc = (t & 31) * 4;
    const float* xp = g_h + (size_t)(n0 + xr)*EMB + xq;
    const float* wp = W + (size_t)wk*EMB + wc;

    float4 xv = *(const float4*)xp;
    float4 wv = *(const float4*)wp;
    Xs[0][xq+0][xr] = xv.x; Xs[0][xq+1][xr] = xv.y;
    Xs[0][xq+2][xr] = xv.z; Xs[0][xq+3][xr] = xv.w;
    *(float4*)&Ws[0][wk][wc] = wv;

    u64 acc[8][4];
    #pragma unroll
    for (int j = 0; j < 8; j++)
        #pragma unroll
        for (int i = 0; i < 4; i++) acc[j][i] = 0ULL;

    int ty = t >> 4, tx = t & 15;
    __syncthreads();

    #pragma unroll 1
    for (int c = 0; c < 16; c++) {
        int cur = c & 1;
        if (c < 15) {
            xv = *(const float4*)(xp + (c+1)*8);
            wv = *(const float4*)(wp + (size_t)(c+1)*8*EMB);
        }
        #pragma unroll
        for (int kk = 0; kk < 8; kk++) {
            float4 a0 = *(const float4*)&Xs[cur][kk][ty*8];
            float4 a1 = *(const float4*)&Xs[cur][kk][ty*8+4];
            ulonglong2 b0 = *(const ulonglong2*)&Ws[cur][kk][tx*8];
            ulonglong2 b1 = *(const ulonglong2*)&Ws[cur][kk][tx*8+4];
            u64 ap[8] = { pk2(a0.x), pk2(a0.y), pk2(a0.z), pk2(a0.w),
                          pk2(a1.x), pk2(a1.y), pk2(a1.z), pk2(a1.w) };
            #pragma unroll
            for (int j = 0; j < 8; j++) {
                fma2(acc[j][0], ap[j], b0.x);
                fma2(acc[j][1], ap[j], b0.y);
                fma2(acc[j][2], ap[j], b1.x);
                fma2(acc[j][3], ap[j], b1.y);
            }
        }
        if (c < 15) {
            int nxt = cur ^ 1;
            Xs[nxt][xq+0][xr] = xv.x; Xs[nxt][xq+1][xr] = xv.y;
            Xs[nxt][xq+2][xr] = xv.z; Xs[nxt][xq+3][xr] = xv.w;
            *(float4*)&Ws[nxt][wk][wc] = wv;
            __syncthreads();
        }
    }

    float bias[8];
    #pragma unroll
    for (int i = 0; i < 8; i++) bias[i] = half ? 0.f : bm[tx*8 + i];
    #pragma unroll
    for (int j = 0; j < 8; j++) {
        float v[8];
        #pragma unroll
        for (int p = 0; p < 4; p++) unpk2(v[2*p], v[2*p+1], acc[j][p]);
        float* o = C + (size_t)(n0 + ty*8 + j)*EMB + tx*8;
        *(float4*)(o)   = make_float4(v[0]+bias[0], v[1]+bias[1], v[2]+bias[2], v[3]+bias[3]);
        *(float4*)(o+4) = make_float4(v[4]+bias[4], v[5]+bias[5], v[6]+bias[6], v[7]+bias[7]);
    }
}

// ----------------------------- edge kernel: kNN layers (deg == 10) -----------------
__global__ __launch_bounds__(256) void k_edge_knn(
    const float* __restrict__ pos_in, float* __restrict__ pos_out,
    const float* __restrict__ Wlast, const float* __restrict__ Wp,
    const float* __restrict__ bp)
{
    int warp = (blockIdx.x*blockDim.x + threadIdx.x) >> 5;
    int lane = threadIdx.x & 31;
    if (warp >= NTOT) return;
    int n = warp;

    float4 p1  = *(const float4*)(g_p1 + (size_t)n*EMB + lane*4);
    float4 wl  = *(const float4*)(Wlast + lane*4);
    float4 wpA = *(const float4*)(Wp + lane*8);
    float4 wpB = *(const float4*)(Wp + lane*8 + 4);

    float px_i = pos_in[2*n], py_i = pos_in[2*n+1];

    int jj = 0; float pjx = 0.f, pjy = 0.f;
    if (lane < KNN) {
        jj = g_src[n*KNN + lane];
        float2 pj = ((const float2*)pos_in)[jj];
        pjx = pj.x; pjy = pj.y;
    }

    float4 macc = make_float4(0.f, 0.f, 0.f, 0.f);
    float g0[KNN], g1[KNN], dxs[KNN], dys[KNN];

    #pragma unroll
    for (int k = 0; k < KNN; k++) {
        int   j  = __shfl_sync(0xffffffffu, jj,  k);
        float dx = px_i - __shfl_sync(0xffffffffu, pjx, k);
        float dy = py_i - __shfl_sync(0xffffffffu, pjy, k);
        float dist = sqrtf(dx*dx + dy*dy);
        dxs[k] = dx; dys[k] = dy;
        float4 p2 = *(const float4*)(g_p2 + (size_t)j*EMB + lane*4);
        float v0 = fmaxf(fmaf(dist, wl.x, p1.x + p2.x), 0.f);
        float v1 = fmaxf(fmaf(dist, wl.y, p1.y + p2.y), 0.f);
        float v2 = fmaxf(fmaf(dist, wl.z, p1.z + p2.z), 0.f);
        float v3 = fmaxf(fmaf(dist, wl.w, p1.w + p2.w), 0.f);
        macc.x += v0; macc.y += v1; macc.z += v2; macc.w += v3;
        g0[k] = v0*wpA.x + v1*wpA.z + v2*wpB.x + v3*wpB.z;
        g1[k] = v0*wpA.y + v1*wpA.w + v2*wpB.y + v3*wpB.w;
    }
    #pragma unroll
    for (int off = 16; off >= 1; off >>= 1) {
        #pragma unroll
        for (int k = 0; k < KNN; k++) {
            g0[k] += __shfl_xor_sync(0xffffffffu, g0[k], off);
            g1[k] += __shfl_xor_sync(0xffffffffu, g1[k], off);
        }
    }
    *(float4*)(g_magg + (size_t)n*EMB + lane*4) = macc;
    if (lane == 0) {
        float bp0 = bp[0], bp1 = bp[1];
        float paccx = 0.f, paccy = 0.f;
        #pragma unroll
        for (int k = 0; k < KNN; k++) {
            paccx = fmaf(dxs[k], fmaxf(g0[k] + bp0, 0.f), paccx);
            paccy = fmaf(dys[k], fmaxf(g1[k] + bp1, 0.f), paccy);
        }
        pos_out[2*n]   = px_i + paccx * 0.1f;
        pos_out[2*n+1] = py_i + paccy * 0.1f;
    }
}

// ----------------------------- edge kernel: layer-0 CSR ----------------------------
__global__ __launch_bounds__(256) void k_edge_csr(
    const int* __restrict__ edge0,
    const float* __restrict__ pos_in, float* __restrict__ pos_out,
    const float* __restrict__ Wlast, const float* __restrict__ Wp,
    const float* __restrict__ bp)
{
    int warp = (blockIdx.x*blockDim.x + threadIdx.x) >> 5;
    int lane = threadIdx.x & 31;
    if (warp >= NTOT) return;
    int n = warp;

    float4 p1  = *(const float4*)(g_p1 + (size_t)n*EMB + lane*4);
    float4 wl  = *(const float4*)(Wlast + lane*4);
    float4 wpA = *(const float4*)(Wp + lane*8);
    float4 wpB = *(const float4*)(Wp + lane*8 + 4);
    float bp0 = bp[0], bp1 = bp[1];

    float px_i = pos_in[2*n], py_i = pos_in[2*n+1];
    int beg = g_rowptr[n], deg = g_rowptr[n+1] - beg;

    float4 macc = make_float4(0.f, 0.f, 0.f, 0.f);
    float paccx = 0.f, paccy = 0.f;

    for (int k = 0; k < deg; k++) {
        int j = edge0[g_perm[beg + k]];
        float dx = px_i - pos_in[2*j];
        float dy = py_i - pos_in[2*j+1];
        float dist = sqrtf(dx*dx + dy*dy);
        float4 p2 = *(const float4*)(g_p2 + (size_t)j*EMB + lane*4);
        float v0 = fmaxf(fmaf(dist, wl.x, p1.x + p2.x), 0.f);
        float v1 = fmaxf(fmaf(dist, wl.y, p1.y + p2.y), 0.f);
        float v2 = fmaxf(fmaf(dist, wl.z, p1.z + p2.z), 0.f);
        float v3 = fmaxf(fmaf(dist, wl.w, p1.w + p2.w), 0.f);
        macc.x += v0; macc.y += v1; macc.z += v2; macc.w += v3;
        float g0 = v0*wpA.x + v1*wpA.z + v2*wpB.x + v3*wpB.z;
        float g1 = v0*wpA.y + v1*wpA.w + v2*wpB.y + v3*wpB.w;
        #pragma unroll
        for (int off = 16; off >= 1; off >>= 1) {
            g0 += __shfl_xor_sync(0xffffffffu, g0, off);
            g1 += __shfl_xor_sync(0xffffffffu, g1, off);
        }
        if (lane == 0) {
            paccx = fmaf(dx, fmaxf(g0 + bp0, 0.f), paccx);
            paccy = fmaf(dy, fmaxf(g1 + bp1, 0.f), paccy);
        }
    }
    *(float4*)(g_magg + (size_t)n*EMB + lane*4) = macc;
    if (lane == 0) {
        float inv = 1.f / fmaxf((float)deg, 1.f);
        pos_out[2*n]   = px_i + paccx*inv;
        pos_out[2*n+1] = py_i + paccy*inv;
    }
}

// ----------------------------- update GEMM (128x128 tile, f32x2) + stats -----------
__global__ __launch_bounds__(256) void k_update(
    const float* __restrict__ Wu, const float* __restrict__ bu)
{
    __shared__ __align__(16) float Xs[2][8][132];
    __shared__ __align__(16) float Ws[2][8][128];
    __shared__ float sCol[128];
    __shared__ float sSq;

    int t = threadIdx.x;
    int n0 = blockIdx.x * 128;

    if (t < 128) sCol[t] = 0.f;
    if (t == 0)  sSq = 0.f;

    int xr = t >> 1, xq = (t & 1) * 4;
    int wk = t >> 5, wc = (t & 31) * 4;
    const float* xpA = g_h    + (size_t)(n0 + xr)*EMB + xq;
    const float* xpB = g_magg + (size_t)(n0 + xr)*EMB + xq;
    const float* wp  = Wu + (size_t)wk*EMB + wc;

    float4 xv = *(const float4*)xpA;
    float4 wv = *(const float4*)wp;
    Xs[0][xq+0][xr] = xv.x; Xs[0][xq+1][xr] = xv.y;
    Xs[0][xq+2][xr] = xv.z; Xs[0][xq+3][xr] = xv.w;
    *(float4*)&Ws[0][wk][wc] = wv;

    u64 acc[8][4];
    #pragma unroll
    for (int j = 0; j < 8; j++)
        #pragma unroll
        for (int i = 0; i < 4; i++) acc[j][i] = 0ULL;

    int ty = t >> 4, tx = t & 15;
    __syncthreads();

    #pragma unroll 1
    for (int c = 0; c < 32; c++) {
        int cur = c & 1;
        if (c < 31) {
            int k0 = (c+1)*8;
            xv = (k0 < 128) ? *(const float4*)(xpA + k0)
                            : *(const float4*)(xpB + (k0 - 128));
            wv = *(const float4*)(wp + (size_t)k0*EMB);
        }
        #pragma unroll
        for (int kk = 0; kk < 8; kk++) {
            float4 a0 = *(const float4*)&Xs[cur][kk][ty*8];
            float4 a1 = *(const float4*)&Xs[cur][kk][ty*8+4];
            ulonglong2 b0 = *(const ulonglong2*)&Ws[cur][kk][tx*8];
            ulonglong2 b1 = *(const ulonglong2*)&Ws[cur][kk][tx*8+4];
            u64 ap[8] = { pk2(a0.x), pk2(a0.y), pk2(a0.z), pk2(a0.w),
                          pk2(a1.x), pk2(a1.y), pk2(a1.z), pk2(a1.w) };
            #pragma unroll
            for (int j = 0; j < 8; j++) {
                fma2(acc[j][0], ap[j], b0.x);
                fma2(acc[j][1], ap[j], b0.y);
                fma2(acc[j][2], ap[j], b1.x);
                fma2(acc[j][3], ap[j], b1.y);
            }
        }
        if (c < 31) {
            int nxt = cur ^ 1;
            Xs[nxt][xq+0][xr] = xv.x; Xs[nxt][xq+1][xr] = xv.y;
            Xs[nxt][xq+2][xr] = xv.z; Xs[nxt][xq+3][xr] = xv.w;
            *(float4*)&Ws[nxt][wk][wc] = wv;
            __syncthreads();
        }
    }

    float bias[8], cps[8];
    #pragma unroll
    for (int i = 0; i < 8; i++) { bias[i] = bu[tx*8 + i]; cps[i] = 0.f; }

    float sq = 0.f;
    #pragma unroll
    for (int j = 0; j < 8; j++) {
        float v[8];
        #pragma unroll
        for (int p = 0; p < 4; p++) unpk2(v[2*p], v[2*p+1], acc[j][p]);
        #pragma unroll
        for (int i = 0; i < 8; i++) {
            v[i] = fmaxf(v[i] + bias[i], 0.f);
            sq = fmaf(v[i], v[i], sq);
            cps[i] += v[i];
        }
        float* o = g_h2 + (size_t)(n0 + ty*8 + j)*EMB + tx*8;
        *(float4*)(o)   = make_float4(v[0], v[1], v[2], v[3]);
        *(float4*)(o+4) = make_float4(v[4], v[5], v[6], v[7]);
    }
    #pragma unroll
    for (int i = 0; i < 8; i++) atomicAdd(&sCol[tx*8 + i], cps[i]);
    #pragma unroll
    for (int off = 16; off >= 1; off >>= 1)
        sq += __shfl_xor_sync(0xffffffffu, sq, off);
    if ((t & 31) == 0) atomicAdd(&sSq, sq);
    __syncthreads();
    if (t < 128) atomicAdd(&g_colsum[t], sCol[t]);
    if (t == 0)  atomicAdd(&g_sumsq, sSq);
}

// ----------------------------- pairnorm finalize / normalize -----------------------
__global__ void k_stats_final()
{
    __shared__ float red[4];
    int t = threadIdx.x;
    float mu = g_colsum[t] * (1.0f/(float)NTOT);
    g_mu[t] = mu;
    float m2 = mu*mu;
    #pragma unroll
    for (int off = 16; off >= 1; off >>= 1)
        m2 += __shfl_xor_sync(0xffffffffu, m2, off);
    if ((t & 31) == 0) red[t >> 5] = m2;
    __syncthreads();
    if (t == 0) {
        float tot = red[0] + red[1] + red[2] + red[3];
        float var = (g_sumsq - (float)NTOT * tot) * (1.0f/(float)NTOT) + 1e-5f;
        g_inv = 1.0f / sqrtf(var);
    }
}
__global__ void k_normalize()
{
    int idx = blockIdx.x*blockDim.x + threadIdx.x;
    if (idx >= NTOT*EMB) return;
    g_h[idx] = (g_h2[idx] - g_mu[idx & 127]) * g_inv;
}

// ----------------------------- readout ---------------------------------------------
__global__ void k_final(const float* __restrict__ W1, const float* __restrict__ b1,
                        const float* __restrict__ W2, const float* __restrict__ b2,
                        float* __restrict__ out)
{
    int g = blockIdx.x, c = threadIdx.x;
    const float* hb = g_h + (size_t)g*NG*EMB;
    float m0 = -3.4e38f, m1 = -3.4e38f, m2 = -3.4e38f, m3 = -3.4e38f;
    for (int n = 0; n < NG; n += 4) {
        m0 = fmaxf(m0, hb[(n+0)*EMB + c]);
        m1 = fmaxf(m1, hb[(n+1)*EMB + c]);
        m2 = fmaxf(m2, hb[(n+2)*EMB + c]);
        m3 = fmaxf(m3, hb[(n+3)*EMB + c]);
    }
    __shared__ float shg[128], shid[128];
    shg[c] = fmaxf(fmaxf(m0, m1), fmaxf(m2, m3));
    __syncthreads();
    float s = b1[c];
    #pragma unroll 4
    for (int k = 0; k < 128; k++) s += shg[k] * W1[k*EMB + c];
    shid[c] = fmaxf(s, 0.f);
    __syncthreads();
    if (c < 2) {
        float o = b2[c];
        for (int k = 0; k < 128; k++) o += shid[k] * W2[2*k + c];
        out[2*g + c] = o;
    }
}

// ----------------------------- launch sequence -------------------------------------
extern "C" void kernel_launch(void* const* d_in, const int* in_sizes, int n_in,
                              void* d_out, int out_size)
{
    const float* h_feat = (const float*)d_in[0];
    const float* pos    = (const float*)d_in[1];
    const int*   edge   = (const int*)  d_in[2];
    const float* W_emb  = (const float*)d_in[3];
    const float* b_emb  = (const float*)d_in[4];
    const float* W_msg  = (const float*)d_in[5];
    const float* b_msg  = (const float*)d_in[6];
    const float* W_pos  = (const float*)d_in[7];
    const float* b_pos  = (const float*)d_in[8];
    const float* W_upd  = (const float*)d_in[9];
    const float* b_upd  = (const float*)d_in[10];
    const float* W1     = (const float*)d_in[11];
    const float* b1     = (const float*)d_in[12];
    const float* W2     = (const float*)d_in[13];
    const float* b2     = (const float*)d_in[14];
    float* out = (float*)d_out;

    static float* posbuf[2] = {nullptr, nullptr};
    if (!posbuf[0]) {
        cudaGetSymbolAddress((void**)&posbuf[0], g_posA);
        cudaGetSymbolAddress((void**)&posbuf[1], g_posB);
    }

    k_init<<<(NTOT*EMB + 255)/256, 256>>>(h_feat, W_emb, b_emb, pos);

    for (int l = 0; l < NLAYER; l++) {
        const float* pos_in  = posbuf[l & 1];
        float*       pos_out = posbuf[(l + 1) & 1];
        if (l == 0) {
            k_count<<<(EALL + 255)/256, 256>>>(edge + EALL);
            k_scan<<<1, 1024>>>();
            k_fill<<<(EALL + 255)/256, 256>>>(edge + EALL);
        } else {
            k_knn<<<BG*(NG/4), 128>>>(pos_in);
        }
        k_pgemm<<<1000, 256>>>(W_msg + (size_t)l*257*EMB, b_msg + l*EMB);
        if (l == 0)
            k_edge_csr<<<(NTOT*32 + 255)/256, 256>>>(
                edge, pos_in, pos_out,
                W_msg + (size_t)l*257*EMB + 256*EMB,
                W_pos + l*EMB*2, b_pos + l*2);
        else
            k_edge_knn<<<(NTOT*32 + 255)/256, 256>>>(
                pos_in, pos_out,
                W_msg + (size_t)l*257*EMB + 256*EMB,
                W_pos + l*EMB*2, b_pos + l*2);
        k_update<<<NTOT/128, 256>>>(W_upd + (size_t)l*256*EMB, b_upd + l*EMB);
        k_stats_final<<<1, 128>>>();
        k_normalize<<<(NTOT*EMB + 255)/256, 256>>>();
    }
    k_final<<<BG, 128>>>(W1, b1, W2, b2, out);
}

// round 12
// speedup vs baseline: 1.7173x; 1.7173x over previous
#include <cuda_runtime.h>
#include <math.h>

#define BG     64
#define NG     1000
#define NTOT   64000
#define KNN    10
#define NLAYER 4
#define EMB    128
#define EALL   (NTOT*KNN)   /* 640000 */

typedef unsigned long long u64;
typedef unsigned int u32;

// ----------------------------- scratch (device globals) -----------------------------
__device__ float g_h   [NTOT*EMB];
__device__ float g_h2  [NTOT*EMB];
__device__ float g_magg[NTOT*EMB];
__device__ float g_p1  [NTOT*EMB];          // h @ Wm1 + bm (dst)
__device__ float g_p2  [NTOT*EMB];          // h @ Wm2      (src)
__device__ float g_posA[NTOT*2];
__device__ float g_posB[NTOT*2];
__device__ int   g_src [EALL];
__device__ int   g_rowptr[NTOT+1];
__device__ int   g_cnt [NTOT];
__device__ int   g_fill[NTOT];
__device__ int   g_perm[EALL];
__device__ float g_colsum[EMB];
__device__ float g_sumsq;
__device__ float g_mu[EMB];
__device__ float g_inv;

// ----------------------------- packed f32x2 helpers --------------------------------
__device__ __forceinline__ u64 pk2(float v){
    u64 r;
    asm("mov.b64 %0, {%1, %1};" : "=l"(r) : "f"(v));
    return r;
}
__device__ __forceinline__ void fma2(u64& d, u64 a, u64 b){
    asm("fma.rn.f32x2 %0, %1, %2, %3;" : "=l"(d) : "l"(a), "l"(b), "l"(d));
}
__device__ __forceinline__ void unpk2(float& lo, float& hi, u64 v){
    asm("mov.b64 {%0, %1}, %2;" : "=f"(lo), "=f"(hi) : "l"(v));
}
__device__ __forceinline__ u64 umin64(u64 a, u64 b){ return a < b ? a : b; }
__device__ __forceinline__ u64 umax64(u64 a, u64 b){ return a < b ? b : a; }

// ----------------------------- init: embed + pos copy + csr zero -------------------
__global__ void k_init(const float* __restrict__ hf, const float* __restrict__ We,
                       const float* __restrict__ be, const float* __restrict__ pos)
{
    int idx = blockIdx.x*blockDim.x + threadIdx.x;
    if (idx < NTOT*2) g_posA[idx] = pos[idx];
    if (idx < NTOT)   { g_cnt[idx] = 0; g_fill[idx] = 0; }
    if (idx >= NTOT*EMB) return;
    int n = idx >> 7, c = idx & 127;
    float s = be[c];
    #pragma unroll
    for (int k = 0; k < 5; k++) s += hf[n*5+k] * We[k*EMB+c];
    g_h[idx] = fmaxf(s, 0.f);
}

// ----------------------------- layer-0 CSR build -----------------------------------
__global__ void k_count(const int* __restrict__ dst)
{
    int e = blockIdx.x*blockDim.x + threadIdx.x;
    if (e < EALL) atomicAdd(&g_cnt[dst[e]], 1);
}
__global__ void k_scan()   // 1 block, 1024 threads
{
    __shared__ int part[1024];
    const int CH = 63;
    int t = threadIdx.x;
    int beg = t*CH, end = min(beg + CH, NTOT);
    int s = 0;
    for (int i = beg; i < end; i++) s += g_cnt[i];
    part[t] = s;
    __syncthreads();
    if (t == 0) {
        int run = 0;
        for (int i = 0; i < 1024; i++) { int v = part[i]; part[i] = run; run += v; }
    }
    __syncthreads();
    int run = part[t];
    for (int i = beg; i < end; i++) { g_rowptr[i] = run; run += g_cnt[i]; }
    if (t == 0) g_rowptr[NTOT] = EALL;
}
__global__ void k_fill(const int* __restrict__ dst)
{
    int e = blockIdx.x*blockDim.x + threadIdx.x;
    if (e >= EALL) return;
    int d = dst[e];
    int o = atomicAdd(&g_fill[d], 1);
    g_perm[g_rowptr[d] + o] = e;
}

// ----------------------------- kNN: branch-free u64-key top-10 ---------------------
// key = (f32_bits(d2) << 32) | j  — d2 >= 0 so u64 order == (d2, j) lexicographic.
// Warp per center node; per-lane sorted top-10 in registers (constant indices only),
// then 10 rounds of warp-wide butterfly min-merge.
__global__ void k_knn(const float* __restrict__ pos)
{
    __shared__ float2 sp[NG];
    int g  = blockIdx.x / (NG/4);
    int nb = blockIdx.x % (NG/4);
    for (int i = threadIdx.x; i < NG; i += 128)
        sp[i] = ((const float2*)pos)[g*NG + i];
    __syncthreads();

    int w = threadIdx.x >> 5, lane = threadIdx.x & 31;
    int i = nb*4 + w;
    float2 pi = sp[i];

    u64 kk[KNN];
    #pragma unroll
    for (int r = 0; r < KNN; r++) kk[r] = ~0ull;

    #pragma unroll 4
    for (int it = 0; it < 32; it++) {
        int j = it*32 + lane;
        u64 cand = ~0ull;
        if (j < NG && j != i) {
            float dx = pi.x - sp[j].x, dy = pi.y - sp[j].y;
            float d2 = dx*dx + dy*dy;
            cand = ((u64)__float_as_uint(d2) << 32) | (u32)j;
        }
        #pragma unroll
        for (int r = 0; r < KNN; r++) {
            u64 lo = umin64(kk[r], cand);
            cand   = umax64(kk[r], cand);
            kk[r]  = lo;
        }
    }

    int base = (g*NG + i)*KNN;
    #pragma unroll
    for (int r = 0; r < KNN; r++) {
        u64 m = kk[0];
        #pragma unroll
        for (int off = 16; off >= 1; off >>= 1)
            m = umin64(m, __shfl_xor_sync(0xffffffffu, m, off));
        if (kk[0] == m) {   // unique real keys -> exactly one lane shifts
            #pragma unroll
            for (int r2 = 0; r2 < KNN-1; r2++) kk[r2] = kk[r2+1];
            kk[KNN-1] = ~0ull;
        }
        if (lane == 0) g_src[base + r] = g*NG + (int)(u32)(m & 0xffffffffu);
    }
}

// ----------------------------- node GEMM: P1/P2 (128x128 tile, f32x2) --------------
__global__ __launch_bounds__(256) void k_pgemm(
    const float* __restrict__ Wm, const float* __restrict__ bm)
{
    __shared__ __align__(16) float Xs[2][8][132];
    __shared__ __align__(16) float Ws[2][8][128];

    int t = threadIdx.x;
    int half = blockIdx.x >= 500;
    int n0 = (blockIdx.x - half*500) * 128;
    const float* W = Wm + (half ? EMB*EMB : 0);
    float* C = half ? g_p2 : g_p1;

    if (blockIdx.x == 0) {
        if (t < 128) g_colsum[t] = 0.f;
        if (t == 0)  g_sumsq = 0.f;
    }

    int xr = t >> 1, xq = (t & 1) * 4;
    int wk = t >> 5, wc = (t & 31) * 4;
    const float* xp = g_h + (size_t)(n0 + xr)*EMB + xq;
    const float* wp = W + (size_t)wk*EMB + wc;

    float4 xv = *(const float4*)xp;
    float4 wv = *(const float4*)wp;
    Xs[0][xq+0][xr] = xv.x; Xs[0][xq+1][xr] = xv.y;
    Xs[0][xq+2][xr] = xv.z; Xs[0][xq+3][xr] = xv.w;
    *(float4*)&Ws[0][wk][wc] = wv;

    u64 acc[8][4];
    #pragma unroll
    for (int j = 0; j < 8; j++)
        #pragma unroll
        for (int i = 0; i < 4; i++) acc[j][i] = 0ULL;

    int ty = t >> 4, tx = t & 15;
    __syncthreads();

    #pragma unroll 1
    for (int c = 0; c < 16; c++) {
        int cur = c & 1;
        if (c < 15) {
            xv = *(const float4*)(xp + (c+1)*8);
            wv = *(const float4*)(wp + (size_t)(c+1)*8*EMB);
        }
        #pragma unroll
        for (int kk = 0; kk < 8; kk++) {
            float4 a0 = *(const float4*)&Xs[cur][kk][ty*8];
            float4 a1 = *(const float4*)&Xs[cur][kk][ty*8+4];
            ulonglong2 b0 = *(const ulonglong2*)&Ws[cur][kk][tx*8];
            ulonglong2 b1 = *(const ulonglong2*)&Ws[cur][kk][tx*8+4];
            u64 ap[8] = { pk2(a0.x), pk2(a0.y), pk2(a0.z), pk2(a0.w),
                          pk2(a1.x), pk2(a1.y), pk2(a1.z), pk2(a1.w) };
            #pragma unroll
            for (int j = 0; j < 8; j++) {
                fma2(acc[j][0], ap[j], b0.x);
                fma2(acc[j][1], ap[j], b0.y);
                fma2(acc[j][2], ap[j], b1.x);
                fma2(acc[j][3], ap[j], b1.y);
            }
        }
        if (c < 15) {
            int nxt = cur ^ 1;
            Xs[nxt][xq+0][xr] = xv.x; Xs[nxt][xq+1][xr] = xv.y;
            Xs[nxt][xq+2][xr] = xv.z; Xs[nxt][xq+3][xr] = xv.w;
            *(float4*)&Ws[nxt][wk][wc] = wv;
            __syncthreads();
        }
    }

    float bias[8];
    #pragma unroll
    for (int i = 0; i < 8; i++) bias[i] = half ? 0.f : bm[tx*8 + i];
    #pragma unroll
    for (int j = 0; j < 8; j++) {
        float v[8];
        #pragma unroll
        for (int p = 0; p < 4; p++) unpk2(v[2*p], v[2*p+1], acc[j][p]);
        float* o = C + (size_t)(n0 + ty*8 + j)*EMB + tx*8;
        *(float4*)(o)   = make_float4(v[0]+bias[0], v[1]+bias[1], v[2]+bias[2], v[3]+bias[3]);
        *(float4*)(o+4) = make_float4(v[4]+bias[4], v[5]+bias[5], v[6]+bias[6], v[7]+bias[7]);
    }
}

// ----------------------------- edge kernel: kNN layers (deg == 10) -----------------
__global__ __launch_bounds__(256) void k_edge_knn(
    const float* __restrict__ pos_in, float* __restrict__ pos_out,
    const float* __restrict__ Wlast, const float* __restrict__ Wp,
    const float* __restrict__ bp)
{
    int warp = (blockIdx.x*blockDim.x + threadIdx.x) >> 5;
    int lane = threadIdx.x & 31;
    if (warp >= NTOT) return;
    int n = warp;

    float4 p1  = *(const float4*)(g_p1 + (size_t)n*EMB + lane*4);
    float4 wl  = *(const float4*)(Wlast + lane*4);
    float4 wpA = *(const float4*)(Wp + lane*8);
    float4 wpB = *(const float4*)(Wp + lane*8 + 4);

    float px_i = pos_in[2*n], py_i = pos_in[2*n+1];

    int jj = 0; float pjx = 0.f, pjy = 0.f;
    if (lane < KNN) {
        jj = g_src[n*KNN + lane];
        float2 pj = ((const float2*)pos_in)[jj];
        pjx = pj.x; pjy = pj.y;
    }

    float4 macc = make_float4(0.f, 0.f, 0.f, 0.f);
    float g0[KNN], g1[KNN], dxs[KNN], dys[KNN];

    #pragma unroll
    for (int k = 0; k < KNN; k++) {
        int   j  = __shfl_sync(0xffffffffu, jj,  k);
        float dx = px_i - __shfl_sync(0xffffffffu, pjx, k);
        float dy = py_i - __shfl_sync(0xffffffffu, pjy, k);
        float dist = sqrtf(dx*dx + dy*dy);
        dxs[k] = dx; dys[k] = dy;
        float4 p2 = *(const float4*)(g_p2 + (size_t)j*EMB + lane*4);
        float v0 = fmaxf(fmaf(dist, wl.x, p1.x + p2.x), 0.f);
        float v1 = fmaxf(fmaf(dist, wl.y, p1.y + p2.y), 0.f);
        float v2 = fmaxf(fmaf(dist, wl.z, p1.z + p2.z), 0.f);
        float v3 = fmaxf(fmaf(dist, wl.w, p1.w + p2.w), 0.f);
        macc.x += v0; macc.y += v1; macc.z += v2; macc.w += v3;
        g0[k] = v0*wpA.x + v1*wpA.z + v2*wpB.x + v3*wpB.z;
        g1[k] = v0*wpA.y + v1*wpA.w + v2*wpB.y + v3*wpB.w;
    }
    #pragma unroll
    for (int off = 16; off >= 1; off >>= 1) {
        #pragma unroll
        for (int k = 0; k < KNN; k++) {
            g0[k] += __shfl_xor_sync(0xffffffffu, g0[k], off);
            g1[k] += __shfl_xor_sync(0xffffffffu, g1[k], off);
        }
    }
    *(float4*)(g_magg + (size_t)n*EMB + lane*4) = macc;
    if (lane == 0) {
        float bp0 = bp[0], bp1 = bp[1];
        float paccx = 0.f, paccy = 0.f;
        #pragma unroll
        for (int k = 0; k < KNN; k++) {
            paccx = fmaf(dxs[k], fmaxf(g0[k] + bp0, 0.f), paccx);
            paccy = fmaf(dys[k], fmaxf(g1[k] + bp1, 0.f), paccy);
        }
        pos_out[2*n]   = px_i + paccx * 0.1f;
        pos_out[2*n+1] = py_i + paccy * 0.1f;
    }
}

// ----------------------------- edge kernel: layer-0 CSR ----------------------------
__global__ __launch_bounds__(256) void k_edge_csr(
    const int* __restrict__ edge0,
    const float* __restrict__ pos_in, float* __restrict__ pos_out,
    const float* __restrict__ Wlast, const float* __restrict__ Wp,
    const float* __restrict__ bp)
{
    int warp = (blockIdx.x*blockDim.x + threadIdx.x) >> 5;
    int lane = threadIdx.x & 31;
    if (warp >= NTOT) return;
    int n = warp;

    float4 p1  = *(const float4*)(g_p1 + (size_t)n*EMB + lane*4);
    float4 wl  = *(const float4*)(Wlast + lane*4);
    float4 wpA = *(const float4*)(Wp + lane*8);
    float4 wpB = *(const float4*)(Wp + lane*8 + 4);
    float bp0 = bp[0], bp1 = bp[1];

    float px_i = pos_in[2*n], py_i = pos_in[2*n+1];
    int beg = g_rowptr[n], deg = g_rowptr[n+1] - beg;

    float4 macc = make_float4(0.f, 0.f, 0.f, 0.f);
    float paccx = 0.f, paccy = 0.f;

    for (int k = 0; k < deg; k++) {
        int j = edge0[g_perm[beg + k]];
        float dx = px_i - pos_in[2*j];
        float dy = py_i - pos_in[2*j+1];
        float dist = sqrtf(dx*dx + dy*dy);
        float4 p2 = *(const float4*)(g_p2 + (size_t)j*EMB + lane*4);
        float v0 = fmaxf(fmaf(dist, wl.x, p1.x + p2.x), 0.f);
        float v1 = fmaxf(fmaf(dist, wl.y, p1.y + p2.y), 0.f);
        float v2 = fmaxf(fmaf(dist, wl.z, p1.z + p2.z), 0.f);
        float v3 = fmaxf(fmaf(dist, wl.w, p1.w + p2.w), 0.f);
        macc.x += v0; macc.y += v1; macc.z += v2; macc.w += v3;
        float g0 = v0*wpA.x + v1*wpA.z + v2*wpB.x + v3*wpB.z;
        float g1 = v0*wpA.y + v1*wpA.w + v2*wpB.y + v3*wpB.w;
        #pragma unroll
        for (int off = 16; off >= 1; off >>= 1) {
            g0 += __shfl_xor_sync(0xffffffffu, g0, off);
            g1 += __shfl_xor_sync(0xffffffffu, g1, off);
        }
        if (lane == 0) {
            paccx = fmaf(dx, fmaxf(g0 + bp0, 0.f), paccx);
            paccy = fmaf(dy, fmaxf(g1 + bp1, 0.f), paccy);
        }
    }
    *(float4*)(g_magg + (size_t)n*EMB + lane*4) = macc;
    if (lane == 0) {
        float inv = 1.f / fmaxf((float)deg, 1.f);
        pos_out[2*n]   = px_i + paccx*inv;
        pos_out[2*n+1] = py_i + paccy*inv;
    }
}

// ----------------------------- update GEMM (128x128 tile, f32x2) + stats -----------
__global__ __launch_bounds__(256) void k_update(
    const float* __restrict__ Wu, const float* __restrict__ bu)
{
    __shared__ __align__(16) float Xs[2][8][132];
    __shared__ __align__(16) float Ws[2][8][128];
    __shared__ float sCol[128];
    __shared__ float sSq;

    int t = threadIdx.x;
    int n0 = blockIdx.x * 128;

    if (t < 128) sCol[t] = 0.f;
    if (t == 0)  sSq = 0.f;

    int xr = t >> 1, xq = (t & 1) * 4;
    int wk = t >> 5, wc = (t & 31) * 4;
    const float* xpA = g_h    + (size_t)(n0 + xr)*EMB + xq;
    const float* xpB = g_magg + (size_t)(n0 + xr)*EMB + xq;
    const float* wp  = Wu + (size_t)wk*EMB + wc;

    float4 xv = *(const float4*)xpA;
    float4 wv = *(const float4*)wp;
    Xs[0][xq+0][xr] = xv.x; Xs[0][xq+1][xr] = xv.y;
    Xs[0][xq+2][xr] = xv.z; Xs[0][xq+3][xr] = xv.w;
    *(float4*)&Ws[0][wk][wc] = wv;

    u64 acc[8][4];
    #pragma unroll
    for (int j = 0; j < 8; j++)
        #pragma unroll
        for (int i = 0; i < 4; i++) acc[j][i] = 0ULL;

    int ty = t >> 4, tx = t & 15;
    __syncthreads();

    #pragma unroll 1
    for (int c = 0; c < 32; c++) {
        int cur = c & 1;
        if (c < 31) {
            int k0 = (c+1)*8;
            xv = (k0 < 128) ? *(const float4*)(xpA + k0)
                            : *(const float4*)(xpB + (k0 - 128));
            wv = *(const float4*)(wp + (size_t)k0*EMB);
        }
        #pragma unroll
        for (int kk = 0; kk < 8; kk++) {
            float4 a0 = *(const float4*)&Xs[cur][kk][ty*8];
            float4 a1 = *(const float4*)&Xs[cur][kk][ty*8+4];
            ulonglong2 b0 = *(const ulonglong2*)&Ws[cur][kk][tx*8];
            ulonglong2 b1 = *(const ulonglong2*)&Ws[cur][kk][tx*8+4];
            u64 ap[8] = { pk2(a0.x), pk2(a0.y), pk2(a0.z), pk2(a0.w),
                          pk2(a1.x), pk2(a1.y), pk2(a1.z), pk2(a1.w) };
            #pragma unroll
            for (int j = 0; j < 8; j++) {
                fma2(acc[j][0], ap[j], b0.x);
                fma2(acc[j][1], ap[j], b0.y);
                fma2(acc[j][2], ap[j], b1.x);
                fma2(acc[j][3], ap[j], b1.y);
            }
        }
        if (c < 31) {
            int nxt = cur ^ 1;
            Xs[nxt][xq+0][xr] = xv.x; Xs[nxt][xq+1][xr] = xv.y;
            Xs[nxt][xq+2][xr] = xv.z; Xs[nxt][xq+3][xr] = xv.w;
            *(float4*)&Ws[nxt][wk][wc] = wv;
            __syncthreads();
        }
    }

    float bias[8], cps[8];
    #pragma unroll
    for (int i = 0; i < 8; i++) { bias[i] = bu[tx*8 + i]; cps[i] = 0.f; }

    float sq = 0.f;
    #pragma unroll
    for (int j = 0; j < 8; j++) {
        float v[8];
        #pragma unroll
        for (int p = 0; p < 4; p++) unpk2(v[2*p], v[2*p+1], acc[j][p]);
        #pragma unroll
        for (int i = 0; i < 8; i++) {
            v[i] = fmaxf(v[i] + bias[i], 0.f);
            sq = fmaf(v[i], v[i], sq);
            cps[i] += v[i];
        }
        float* o = g_h2 + (size_t)(n0 + ty*8 + j)*EMB + tx*8;
        *(float4*)(o)   = make_float4(v[0], v[1], v[2], v[3]);
        *(float4*)(o+4) = make_float4(v[4], v[5], v[6], v[7]);
    }
    #pragma unroll
    for (int i = 0; i < 8; i++) atomicAdd(&sCol[tx*8 + i], cps[i]);
    #pragma unroll
    for (int off = 16; off >= 1; off >>= 1)
        sq += __shfl_xor_sync(0xffffffffu, sq, off);
    if ((t & 31) == 0) atomicAdd(&sSq, sq);
    __syncthreads();
    if (t < 128) atomicAdd(&g_colsum[t], sCol[t]);
    if (t == 0)  atomicAdd(&g_sumsq, sSq);
}

// ----------------------------- pairnorm finalize / normalize -----------------------
__global__ void k_stats_final()
{
    __shared__ float red[4];
    int t = threadIdx.x;
    float mu = g_colsum[t] * (1.0f/(float)NTOT);
    g_mu[t] = mu;
    float m2 = mu*mu;
    #pragma unroll
    for (int off = 16; off >= 1; off >>= 1)
        m2 += __shfl_xor_sync(0xffffffffu, m2, off);
    if ((t & 31) == 0) red[t >> 5] = m2;
    __syncthreads();
    if (t == 0) {
        float tot = red[0] + red[1] + red[2] + red[3];
        float var = (g_sumsq - (float)NTOT * tot) * (1.0f/(float)NTOT) + 1e-5f;
        g_inv = 1.0f / sqrtf(var);
    }
}
__global__ void k_normalize()
{
    int idx = blockIdx.x*blockDim.x + threadIdx.x;
    if (idx >= NTOT*EMB) return;
    g_h[idx] = (g_h2[idx] - g_mu[idx & 127]) * g_inv;
}

// ----------------------------- readout ---------------------------------------------
__global__ void k_final(const float* __restrict__ W1, const float* __restrict__ b1,
                        const float* __restrict__ W2, const float* __restrict__ b2,
                        float* __restrict__ out)
{
    int g = blockIdx.x, c = threadIdx.x;
    const float* hb = g_h + (size_t)g*NG*EMB;
    float m0 = -3.4e38f, m1 = -3.4e38f, m2 = -3.4e38f, m3 = -3.4e38f;
    for (int n = 0; n < NG; n += 4) {
        m0 = fmaxf(m0, hb[(n+0)*EMB + c]);
        m1 = fmaxf(m1, hb[(n+1)*EMB + c]);
        m2 = fmaxf(m2, hb[(n+2)*EMB + c]);
        m3 = fmaxf(m3, hb[(n+3)*EMB + c]);
    }
    __shared__ float shg[128], shid[128];
    shg[c] = fmaxf(fmaxf(m0, m1), fmaxf(m2, m3));
    __syncthreads();
    float s = b1[c];
    #pragma unroll 4
    for (int k = 0; k < 128; k++) s += shg[k] * W1[k*EMB + c];
    shid[c] = fmaxf(s, 0.f);
    __syncthreads();
    if (c < 2) {
        float o = b2[c];
        for (int k = 0; k < 128; k++) o += shid[k] * W2[2*k + c];
        out[2*g + c] = o;
    }
}

// ----------------------------- launch sequence -------------------------------------
extern "C" void kernel_launch(void* const* d_in, const int* in_sizes, int n_in,
                              void* d_out, int out_size)
{
    const float* h_feat = (const float*)d_in[0];
    const float* pos    = (const float*)d_in[1];
    const int*   edge   = (const int*)  d_in[2];
    const float* W_emb  = (const float*)d_in[3];
    const float* b_emb  = (const float*)d_in[4];
    const float* W_msg  = (const float*)d_in[5];
    const float* b_msg  = (const float*)d_in[6];
    const float* W_pos  = (const float*)d_in[7];
    const float* b_pos  = (const float*)d_in[8];
    const float* W_upd  = (const float*)d_in[9];
    const float* b_upd  = (const float*)d_in[10];
    const float* W1     = (const float*)d_in[11];
    const float* b1     = (const float*)d_in[12];
    const float* W2     = (const float*)d_in[13];
    const float* b2     = (const float*)d_in[14];
    float* out = (float*)d_out;

    static float* posbuf[2] = {nullptr, nullptr};
    if (!posbuf[0]) {
        cudaGetSymbolAddress((void**)&posbuf[0], g_posA);
        cudaGetSymbolAddress((void**)&posbuf[1], g_posB);
    }

    k_init<<<(NTOT*EMB + 255)/256, 256>>>(h_feat, W_emb, b_emb, pos);

    for (int l = 0; l < NLAYER; l++) {
        const float* pos_in  = posbuf[l & 1];
        float*       pos_out = posbuf[(l + 1) & 1];
        if (l == 0) {
            // pgemm before fill so ncu -s 5 window captures k_pgemm
            k_count<<<(EALL + 255)/256, 256>>>(edge + EALL);
            k_scan<<<1, 1024>>>();
            k_pgemm<<<1000, 256>>>(W_msg + (size_t)l*257*EMB, b_msg + l*EMB);
            k_fill<<<(EALL + 255)/256, 256>>>(edge + EALL);
            k_edge_csr<<<(NTOT*32 + 255)/256, 256>>>(
                edge, pos_in, pos_out,
                W_msg + (size_t)l*257*EMB + 256*EMB,
                W_pos + l*EMB*2, b_pos + l*2);
        } else {
            k_knn<<<BG*(NG/4), 128>>>(pos_in);
            k_pgemm<<<1000, 256>>>(W_msg + (size_t)l*257*EMB, b_msg + l*EMB);
            k_edge_knn<<<(NTOT*32 + 255)/256, 256>>>(
                pos_in, pos_out,
                W_msg + (size_t)l*257*EMB + 256*EMB,
                W_pos + l*EMB*2, b_pos + l*2);
        }
        k_update<<<NTOT/128, 256>>>(W_upd + (size_t)l*256*EMB, b_upd + l*EMB);
        k_stats_final<<<1, 128>>>();
        k_normalize<<<(NTOT*EMB + 255)/256, 256>>>();
    }
    k_final<<<BG, 128>>>(W1, b1, W2, b2, out);
}

// round 13
// speedup vs baseline: 1.8034x; 1.0501x over previous
#include <cuda_runtime.h>
#include <math.h>

#define BG     64
#define NG     1000
#define NTOT   64000
#define KNN    10
#define NLAYER 4
#define EMB    128
#define EALL   (NTOT*KNN)   /* 640000 */

typedef unsigned long long u64;
typedef unsigned int u32;

// ----------------------------- scratch (device globals) -----------------------------
__device__ float g_h   [NTOT*EMB];          // h buffer 0 (ping-pong)
__device__ float g_h2  [NTOT*EMB];          // h buffer 1 (ping-pong)
__device__ float g_magg[NTOT*EMB];
__device__ float g_p1  [NTOT*EMB];          // h_norm @ Wm1 + bm (dst)
__device__ float g_p2  [NTOT*EMB];          // h_norm @ Wm2      (src)
__device__ float g_posA[NTOT*2];
__device__ float g_posB[NTOT*2];
__device__ int   g_src [EALL];
__device__ int   g_rowptr[NTOT+1];
__device__ int   g_cnt [NTOT];
__device__ int   g_fill[NTOT];
__device__ int   g_perm[EALL];
__device__ float g_colsum[EMB];
__device__ float g_sumsq;
__device__ float g_mu[EMB];
__device__ float g_inv;

// ----------------------------- packed f32x2 helpers --------------------------------
__device__ __forceinline__ u64 pk2(float v){
    u64 r;
    asm("mov.b64 %0, {%1, %1};" : "=l"(r) : "f"(v));
    return r;
}
__device__ __forceinline__ void fma2(u64& d, u64 a, u64 b){
    asm("fma.rn.f32x2 %0, %1, %2, %3;" : "=l"(d) : "l"(a), "l"(b), "l"(d));
}
__device__ __forceinline__ void unpk2(float& lo, float& hi, u64 v){
    asm("mov.b64 {%0, %1}, %2;" : "=f"(lo), "=f"(hi) : "l"(v));
}
__device__ __forceinline__ u64 umin64(u64 a, u64 b){ return a < b ? a : b; }
__device__ __forceinline__ u64 umax64(u64 a, u64 b){ return a < b ? b : a; }

// ----------------------------- init: embed + pos copy + csr zero + norm identity ---
__global__ void k_init(const float* __restrict__ hf, const float* __restrict__ We,
                       const float* __restrict__ be, const float* __restrict__ pos)
{
    int idx = blockIdx.x*blockDim.x + threadIdx.x;
    if (idx < NTOT*2) g_posA[idx] = pos[idx];
    if (idx < NTOT)   { g_cnt[idx] = 0; g_fill[idx] = 0; }
    if (idx < 128)    g_mu[idx] = 0.f;
    if (idx == 0)     g_inv = 1.f;
    if (idx >= NTOT*EMB) return;
    int n = idx >> 7, c = idx & 127;
    float s = be[c];
    #pragma unroll
    for (int k = 0; k < 5; k++) s += hf[n*5+k] * We[k*EMB+c];
    g_h[idx] = fmaxf(s, 0.f);
}

// ----------------------------- layer-0 CSR build -----------------------------------
__global__ void k_count(const int* __restrict__ dst)
{
    int e = blockIdx.x*blockDim.x + threadIdx.x;
    if (e < EALL) atomicAdd(&g_cnt[dst[e]], 1);
}
__global__ void k_scan()   // 1 block, 1024 threads
{
    __shared__ int part[1024];
    const int CH = 63;
    int t = threadIdx.x;
    int beg = t*CH, end = min(beg + CH, NTOT);
    int s = 0;
    for (int i = beg; i < end; i++) s += g_cnt[i];
    part[t] = s;
    __syncthreads();
    if (t == 0) {
        int run = 0;
        for (int i = 0; i < 1024; i++) { int v = part[i]; part[i] = run; run += v; }
    }
    __syncthreads();
    int run = part[t];
    for (int i = beg; i < end; i++) { g_rowptr[i] = run; run += g_cnt[i]; }
    if (t == 0) g_rowptr[NTOT] = EALL;
}
__global__ void k_fill(const int* __restrict__ dst)
{
    int e = blockIdx.x*blockDim.x + threadIdx.x;
    if (e >= EALL) return;
    int d = dst[e];
    int o = atomicAdd(&g_fill[d], 1);
    g_perm[g_rowptr[d] + o] = e;
}

// ----------------------------- kNN: branch-free u64-key top-10 ---------------------
__global__ void k_knn(const float* __restrict__ pos)
{
    __shared__ float2 sp[NG];
    int g  = blockIdx.x / (NG/4);
    int nb = blockIdx.x % (NG/4);
    for (int i = threadIdx.x; i < NG; i += 128)
        sp[i] = ((const float2*)pos)[g*NG + i];
    __syncthreads();

    int w = threadIdx.x >> 5, lane = threadIdx.x & 31;
    int i = nb*4 + w;
    float2 pi = sp[i];

    u64 kk[KNN];
    #pragma unroll
    for (int r = 0; r < KNN; r++) kk[r] = ~0ull;

    #pragma unroll 4
    for (int it = 0; it < 32; it++) {
        int j = it*32 + lane;
        u64 cand = ~0ull;
        if (j < NG && j != i) {
            float dx = pi.x - sp[j].x, dy = pi.y - sp[j].y;
            float d2 = dx*dx + dy*dy;
            cand = ((u64)__float_as_uint(d2) << 32) | (u32)j;
        }
        #pragma unroll
        for (int r = 0; r < KNN; r++) {
            u64 lo = umin64(kk[r], cand);
            cand   = umax64(kk[r], cand);
            kk[r]  = lo;
        }
    }

    int base = (g*NG + i)*KNN;
    #pragma unroll
    for (int r = 0; r < KNN; r++) {
        u64 m = kk[0];
        #pragma unroll
        for (int off = 16; off >= 1; off >>= 1)
            m = umin64(m, __shfl_xor_sync(0xffffffffu, m, off));
        if (kk[0] == m) {
            #pragma unroll
            for (int r2 = 0; r2 < KNN-1; r2++) kk[r2] = kk[r2+1];
            kk[KNN-1] = ~0ull;
        }
        if (lane == 0) g_src[base + r] = g*NG + (int)(u32)(m & 0xffffffffu);
    }
}

// ----------------------------- node GEMM: P1/P2 (16x8 tile, f32x2, fused norm) -----
// 128 threads; block tile 128x128. bid<500 -> P1 = hnorm@Wm1 + bm ; else P2.
__global__ __launch_bounds__(128) void k_pgemm(
    const float* __restrict__ Wm, const float* __restrict__ bm,
    const float* __restrict__ hin)
{
    __shared__ __align__(16) float Xs[2][8][132];
    __shared__ __align__(16) float Ws[2][8][128];
    __shared__ float sOff[128];

    int t = threadIdx.x;
    int half = blockIdx.x >= 500;
    int n0 = (blockIdx.x - half*500) * 128;
    const float* W = Wm + (half ? EMB*EMB : 0);
    float* C = half ? g_p2 : g_p1;

    if (blockIdx.x == 0) {           // zero stats for the k_update after us
        g_colsum[t] = 0.f;
        if (t == 0) g_sumsq = 0.f;
    }
    float inv = g_inv;
    sOff[t] = -g_mu[t]*inv;

    const float* xp = hin + (size_t)(n0 + t)*EMB;
    const float* wp = W + (size_t)(t>>4)*EMB + (t&15)*8;

    float4 xa = *(const float4*)(xp);
    float4 xb = *(const float4*)(xp + 4);
    float4 wa = *(const float4*)(wp);
    float4 wb = *(const float4*)(wp + 4);

    u64 acc[16][4];
    #pragma unroll
    for (int j = 0; j < 16; j++)
        #pragma unroll
        for (int i = 0; i < 4; i++) acc[j][i] = 0ULL;

    int ry = (t>>4)*16, cx = (t&15)*8;
    __syncthreads();   // sOff visible

    // store chunk 0 (with norm)
    Xs[0][0][t] = fmaf(xa.x, inv, sOff[0]); Xs[0][1][t] = fmaf(xa.y, inv, sOff[1]);
    Xs[0][2][t] = fmaf(xa.z, inv, sOff[2]); Xs[0][3][t] = fmaf(xa.w, inv, sOff[3]);
    Xs[0][4][t] = fmaf(xb.x, inv, sOff[4]); Xs[0][5][t] = fmaf(xb.y, inv, sOff[5]);
    Xs[0][6][t] = fmaf(xb.z, inv, sOff[6]); Xs[0][7][t] = fmaf(xb.w, inv, sOff[7]);
    *(float4*)&Ws[0][t>>4][cx]     = wa;
    *(float4*)&Ws[0][t>>4][cx + 4] = wb;
    __syncthreads();

    #pragma unroll 1
    for (int c = 0; c < 16; c++) {
        int cur = c & 1;
        if (c < 15) {
            xa = *(const float4*)(xp + (c+1)*8);
            xb = *(const float4*)(xp + (c+1)*8 + 4);
            wa = *(const float4*)(wp + (size_t)(c+1)*8*EMB);
            wb = *(const float4*)(wp + (size_t)(c+1)*8*EMB + 4);
        }
        #pragma unroll
        for (int kk = 0; kk < 8; kk++) {
            float4 a0 = *(const float4*)&Xs[cur][kk][ry];
            float4 a1 = *(const float4*)&Xs[cur][kk][ry+4];
            float4 a2 = *(const float4*)&Xs[cur][kk][ry+8];
            float4 a3 = *(const float4*)&Xs[cur][kk][ry+12];
            ulonglong2 b0 = *(const ulonglong2*)&Ws[cur][kk][cx];
            ulonglong2 b1 = *(const ulonglong2*)&Ws[cur][kk][cx+4];
            float av[16] = {a0.x,a0.y,a0.z,a0.w, a1.x,a1.y,a1.z,a1.w,
                            a2.x,a2.y,a2.z,a2.w, a3.x,a3.y,a3.z,a3.w};
            #pragma unroll
            for (int j = 0; j < 16; j++) {
                u64 ap = pk2(av[j]);
                fma2(acc[j][0], ap, b0.x);
                fma2(acc[j][1], ap, b0.y);
                fma2(acc[j][2], ap, b1.x);
                fma2(acc[j][3], ap, b1.y);
            }
        }
        if (c < 15) {
            int nxt = cur ^ 1;
            int k0 = (c+1)*8;
            Xs[nxt][0][t] = fmaf(xa.x, inv, sOff[k0+0]); Xs[nxt][1][t] = fmaf(xa.y, inv, sOff[k0+1]);
            Xs[nxt][2][t] = fmaf(xa.z, inv, sOff[k0+2]); Xs[nxt][3][t] = fmaf(xa.w, inv, sOff[k0+3]);
            Xs[nxt][4][t] = fmaf(xb.x, inv, sOff[k0+4]); Xs[nxt][5][t] = fmaf(xb.y, inv, sOff[k0+5]);
            Xs[nxt][6][t] = fmaf(xb.z, inv, sOff[k0+6]); Xs[nxt][7][t] = fmaf(xb.w, inv, sOff[k0+7]);
            *(float4*)&Ws[nxt][t>>4][cx]     = wa;
            *(float4*)&Ws[nxt][t>>4][cx + 4] = wb;
            __syncthreads();
        }
    }

    float bias[8];
    #pragma unroll
    for (int i = 0; i < 8; i++) bias[i] = half ? 0.f : bm[cx + i];
    #pragma unroll
    for (int j = 0; j < 16; j++) {
        float v[8];
        #pragma unroll
        for (int p = 0; p < 4; p++) unpk2(v[2*p], v[2*p+1], acc[j][p]);
        float* o = C + (size_t)(n0 + ry + j)*EMB + cx;
        *(float4*)(o)   = make_float4(v[0]+bias[0], v[1]+bias[1], v[2]+bias[2], v[3]+bias[3]);
        *(float4*)(o+4) = make_float4(v[4]+bias[4], v[5]+bias[5], v[6]+bias[6], v[7]+bias[7]);
    }
}

// ----------------------------- edge kernel: kNN layers (deg == 10) -----------------
__global__ __launch_bounds__(256) void k_edge_knn(
    const float* __restrict__ pos_in, float* __restrict__ pos_out,
    const float* __restrict__ Wlast, const float* __restrict__ Wp,
    const float* __restrict__ bp)
{
    int warp = (blockIdx.x*blockDim.x + threadIdx.x) >> 5;
    int lane = threadIdx.x & 31;
    if (warp >= NTOT) return;
    int n = warp;

    float4 p1  = *(const float4*)(g_p1 + (size_t)n*EMB + lane*4);
    float4 wl  = *(const float4*)(Wlast + lane*4);
    float4 wpA = *(const float4*)(Wp + lane*8);
    float4 wpB = *(const float4*)(Wp + lane*8 + 4);

    float px_i = pos_in[2*n], py_i = pos_in[2*n+1];

    int jj = 0; float pjx = 0.f, pjy = 0.f;
    if (lane < KNN) {
        jj = g_src[n*KNN + lane];
        float2 pj = ((const float2*)pos_in)[jj];
        pjx = pj.x; pjy = pj.y;
    }

    float4 macc = make_float4(0.f, 0.f, 0.f, 0.f);
    float g0[KNN], g1[KNN], dxs[KNN], dys[KNN];

    #pragma unroll
    for (int k = 0; k < KNN; k++) {
        int   j  = __shfl_sync(0xffffffffu, jj,  k);
        float dx = px_i - __shfl_sync(0xffffffffu, pjx, k);
        float dy = py_i - __shfl_sync(0xffffffffu, pjy, k);
        float dist = sqrtf(dx*dx + dy*dy);
        dxs[k] = dx; dys[k] = dy;
        float4 p2 = *(const float4*)(g_p2 + (size_t)j*EMB + lane*4);
        float v0 = fmaxf(fmaf(dist, wl.x, p1.x + p2.x), 0.f);
        float v1 = fmaxf(fmaf(dist, wl.y, p1.y + p2.y), 0.f);
        float v2 = fmaxf(fmaf(dist, wl.z, p1.z + p2.z), 0.f);
        float v3 = fmaxf(fmaf(dist, wl.w, p1.w + p2.w), 0.f);
        macc.x += v0; macc.y += v1; macc.z += v2; macc.w += v3;
        g0[k] = v0*wpA.x + v1*wpA.z + v2*wpB.x + v3*wpB.z;
        g1[k] = v0*wpA.y + v1*wpA.w + v2*wpB.y + v3*wpB.w;
    }
    #pragma unroll
    for (int off = 16; off >= 1; off >>= 1) {
        #pragma unroll
        for (int k = 0; k < KNN; k++) {
            g0[k] += __shfl_xor_sync(0xffffffffu, g0[k], off);
            g1[k] += __shfl_xor_sync(0xffffffffu, g1[k], off);
        }
    }
    *(float4*)(g_magg + (size_t)n*EMB + lane*4) = macc;
    if (lane == 0) {
        float bp0 = bp[0], bp1 = bp[1];
        float paccx = 0.f, paccy = 0.f;
        #pragma unroll
        for (int k = 0; k < KNN; k++) {
            paccx = fmaf(dxs[k], fmaxf(g0[k] + bp0, 0.f), paccx);
            paccy = fmaf(dys[k], fmaxf(g1[k] + bp1, 0.f), paccy);
        }
        pos_out[2*n]   = px_i + paccx * 0.1f;
        pos_out[2*n+1] = py_i + paccy * 0.1f;
    }
}

// ----------------------------- edge kernel: layer-0 CSR ----------------------------
__global__ __launch_bounds__(256) void k_edge_csr(
    const int* __restrict__ edge0,
    const float* __restrict__ pos_in, float* __restrict__ pos_out,
    const float* __restrict__ Wlast, const float* __restrict__ Wp,
    const float* __restrict__ bp)
{
    int warp = (blockIdx.x*blockDim.x + threadIdx.x) >> 5;
    int lane = threadIdx.x & 31;
    if (warp >= NTOT) return;
    int n = warp;

    float4 p1  = *(const float4*)(g_p1 + (size_t)n*EMB + lane*4);
    float4 wl  = *(const float4*)(Wlast + lane*4);
    float4 wpA = *(const float4*)(Wp + lane*8);
    float4 wpB = *(const float4*)(Wp + lane*8 + 4);
    float bp0 = bp[0], bp1 = bp[1];

    float px_i = pos_in[2*n], py_i = pos_in[2*n+1];
    int beg = g_rowptr[n], deg = g_rowptr[n+1] - beg;

    float4 macc = make_float4(0.f, 0.f, 0.f, 0.f);
    float paccx = 0.f, paccy = 0.f;

    for (int k = 0; k < deg; k++) {
        int j = edge0[g_perm[beg + k]];
        float dx = px_i - pos_in[2*j];
        float dy = py_i - pos_in[2*j+1];
        float dist = sqrtf(dx*dx + dy*dy);
        float4 p2 = *(const float4*)(g_p2 + (size_t)j*EMB + lane*4);
        float v0 = fmaxf(fmaf(dist, wl.x, p1.x + p2.x), 0.f);
        float v1 = fmaxf(fmaf(dist, wl.y, p1.y + p2.y), 0.f);
        float v2 = fmaxf(fmaf(dist, wl.z, p1.z + p2.z), 0.f);
        float v3 = fmaxf(fmaf(dist, wl.w, p1.w + p2.w), 0.f);
        macc.x += v0; macc.y += v1; macc.z += v2; macc.w += v3;
        float g0 = v0*wpA.x + v1*wpA.z + v2*wpB.x + v3*wpB.z;
        float g1 = v0*wpA.y + v1*wpA.w + v2*wpB.y + v3*wpB.w;
        #pragma unroll
        for (int off = 16; off >= 1; off >>= 1) {
            g0 += __shfl_xor_sync(0xffffffffu, g0, off);
            g1 += __shfl_xor_sync(0xffffffffu, g1, off);
        }
        if (lane == 0) {
            paccx = fmaf(dx, fmaxf(g0 + bp0, 0.f), paccx);
            paccy = fmaf(dy, fmaxf(g1 + bp1, 0.f), paccy);
        }
    }
    *(float4*)(g_magg + (size_t)n*EMB + lane*4) = macc;
    if (lane == 0) {
        float inv = 1.f / fmaxf((float)deg, 1.f);
        pos_out[2*n]   = px_i + paccx*inv;
        pos_out[2*n+1] = py_i + paccy*inv;
    }
}

// ----------------------------- update GEMM (16x8 tile, f32x2, fused norm) ----------
// 128 threads; block tile 128x128; K=256 ([h_norm | magg]). Writes hout + stats.
__global__ __launch_bounds__(128) void k_update(
    const float* __restrict__ Wu, const float* __restrict__ bu,
    const float* __restrict__ hin, float* __restrict__ hout)
{
    __shared__ __align__(16) float Xs[2][8][132];
    __shared__ __align__(16) float Ws[2][8][128];
    __shared__ float sOff[128];
    __shared__ float sCol[128];
    __shared__ float sSq;

    int t = threadIdx.x;
    int n0 = blockIdx.x * 128;

    sCol[t] = 0.f;
    if (t == 0) sSq = 0.f;
    float inv = g_inv;
    sOff[t] = -g_mu[t]*inv;

    const float* xpA = hin    + (size_t)(n0 + t)*EMB;
    const float* xpB = g_magg + (size_t)(n0 + t)*EMB;
    const float* wp  = Wu + (size_t)(t>>4)*EMB + (t&15)*8;

    float4 xa = *(const float4*)(xpA);
    float4 xb = *(const float4*)(xpA + 4);
    float4 wa = *(const float4*)(wp);
    float4 wb = *(const float4*)(wp + 4);

    u64 acc[16][4];
    #pragma unroll
    for (int j = 0; j < 16; j++)
        #pragma unroll
        for (int i = 0; i < 4; i++) acc[j][i] = 0ULL;

    int ry = (t>>4)*16, cx = (t&15)*8;
    __syncthreads();

    Xs[0][0][t] = fmaf(xa.x, inv, sOff[0]); Xs[0][1][t] = fmaf(xa.y, inv, sOff[1]);
    Xs[0][2][t] = fmaf(xa.z, inv, sOff[2]); Xs[0][3][t] = fmaf(xa.w, inv, sOff[3]);
    Xs[0][4][t] = fmaf(xb.x, inv, sOff[4]); Xs[0][5][t] = fmaf(xb.y, inv, sOff[5]);
    Xs[0][6][t] = fmaf(xb.z, inv, sOff[6]); Xs[0][7][t] = fmaf(xb.w, inv, sOff[7]);
    *(float4*)&Ws[0][t>>4][cx]     = wa;
    *(float4*)&Ws[0][t>>4][cx + 4] = wb;
    __syncthreads();

    #pragma unroll 1
    for (int c = 0; c < 32; c++) {
        int cur = c & 1;
        int k1 = (c+1)*8;
        bool nrm = (k1 < 128);
        if (c < 31) {
            const float* src = nrm ? (xpA + k1) : (xpB + (k1 - 128));
            xa = *(const float4*)(src);
            xb = *(const float4*)(src + 4);
            wa = *(const float4*)(wp + (size_t)k1*EMB);
            wb = *(const float4*)(wp + (size_t)k1*EMB + 4);
        }
        #pragma unroll
        for (int kk = 0; kk < 8; kk++) {
            float4 a0 = *(const float4*)&Xs[cur][kk][ry];
            float4 a1 = *(const float4*)&Xs[cur][kk][ry+4];
            float4 a2 = *(const float4*)&Xs[cur][kk][ry+8];
            float4 a3 = *(const float4*)&Xs[cur][kk][ry+12];
            ulonglong2 b0 = *(const ulonglong2*)&Ws[cur][kk][cx];
            ulonglong2 b1 = *(const ulonglong2*)&Ws[cur][kk][cx+4];
            float av[16] = {a0.x,a0.y,a0.z,a0.w, a1.x,a1.y,a1.z,a1.w,
                            a2.x,a2.y,a2.z,a2.w, a3.x,a3.y,a3.z,a3.w};
            #pragma unroll
            for (int j = 0; j < 16; j++) {
                u64 ap = pk2(av[j]);
                fma2(acc[j][0], ap, b0.x);
                fma2(acc[j][1], ap, b0.y);
                fma2(acc[j][2], ap, b1.x);
                fma2(acc[j][3], ap, b1.y);
            }
        }
        if (c < 31) {
            int nxt = cur ^ 1;
            float o0 = nrm ? sOff[k1+0] : 0.f, o1 = nrm ? sOff[k1+1] : 0.f;
            float o2 = nrm ? sOff[k1+2] : 0.f, o3 = nrm ? sOff[k1+3] : 0.f;
            float o4 = nrm ? sOff[k1+4] : 0.f, o5 = nrm ? sOff[k1+5] : 0.f;
            float o6 = nrm ? sOff[k1+6] : 0.f, o7 = nrm ? sOff[k1+7] : 0.f;
            float iv = nrm ? inv : 1.f;
            Xs[nxt][0][t] = fmaf(xa.x, iv, o0); Xs[nxt][1][t] = fmaf(xa.y, iv, o1);
            Xs[nxt][2][t] = fmaf(xa.z, iv, o2); Xs[nxt][3][t] = fmaf(xa.w, iv, o3);
            Xs[nxt][4][t] = fmaf(xb.x, iv, o4); Xs[nxt][5][t] = fmaf(xb.y, iv, o5);
            Xs[nxt][6][t] = fmaf(xb.z, iv, o6); Xs[nxt][7][t] = fmaf(xb.w, iv, o7);
            *(float4*)&Ws[nxt][t>>4][cx]     = wa;
            *(float4*)&Ws[nxt][t>>4][cx + 4] = wb;
            __syncthreads();
        }
    }

    float bias[8], cps[8];
    #pragma unroll
    for (int i = 0; i < 8; i++) { bias[i] = bu[cx + i]; cps[i] = 0.f; }

    float sq = 0.f;
    #pragma unroll
    for (int j = 0; j < 16; j++) {
        float v[8];
        #pragma unroll
        for (int p = 0; p < 4; p++) unpk2(v[2*p], v[2*p+1], acc[j][p]);
        #pragma unroll
        for (int i = 0; i < 8; i++) {
            v[i] = fmaxf(v[i] + bias[i], 0.f);
            sq = fmaf(v[i], v[i], sq);
            cps[i] += v[i];
        }
        float* o = hout + (size_t)(n0 + ry + j)*EMB + cx;
        *(float4*)(o)   = make_float4(v[0], v[1], v[2], v[3]);
        *(float4*)(o+4) = make_float4(v[4], v[5], v[6], v[7]);
    }
    #pragma unroll
    for (int i = 0; i < 8; i++) atomicAdd(&sCol[cx + i], cps[i]);
    #pragma unroll
    for (int off = 16; off >= 1; off >>= 1)
        sq += __shfl_xor_sync(0xffffffffu, sq, off);
    if ((t & 31) == 0) atomicAdd(&sSq, sq);
    __syncthreads();
    atomicAdd(&g_colsum[t], sCol[t]);
    if (t == 0) atomicAdd(&g_sumsq, sSq);
}

// ----------------------------- pairnorm finalize -----------------------------------
__global__ void k_stats_final()
{
    __shared__ float red[4];
    int t = threadIdx.x;
    float mu = g_colsum[t] * (1.0f/(float)NTOT);
    g_mu[t] = mu;
    float m2 = mu*mu;
    #pragma unroll
    for (int off = 16; off >= 1; off >>= 1)
        m2 += __shfl_xor_sync(0xffffffffu, m2, off);
    if ((t & 31) == 0) red[t >> 5] = m2;
    __syncthreads();
    if (t == 0) {
        float tot = red[0] + red[1] + red[2] + red[3];
        float var = (g_sumsq - (float)NTOT * tot) * (1.0f/(float)NTOT) + 1e-5f;
        g_inv = 1.0f / sqrtf(var);
    }
}

// ----------------------------- readout (applies final pairnorm after pooling) ------
__global__ void k_final(const float* __restrict__ hin,
                        const float* __restrict__ W1, const float* __restrict__ b1,
                        const float* __restrict__ W2, const float* __restrict__ b2,
                        float* __restrict__ out)
{
    int g = blockIdx.x, c = threadIdx.x;
    const float* hb = hin + (size_t)g*NG*EMB;
    float m0 = -3.4e38f, m1 = -3.4e38f, m2 = -3.4e38f, m3 = -3.4e38f;
    for (int n = 0; n < NG; n += 4) {
        m0 = fmaxf(m0, hb[(n+0)*EMB + c]);
        m1 = fmaxf(m1, hb[(n+1)*EMB + c]);
        m2 = fmaxf(m2, hb[(n+2)*EMB + c]);
        m3 = fmaxf(m3, hb[(n+3)*EMB + c]);
    }
    __shared__ float shg[128], shid[128];
    shg[c] = (fmaxf(fmaxf(m0, m1), fmaxf(m2, m3)) - g_mu[c]) * g_inv;
    __syncthreads();
    float s = b1[c];
    #pragma unroll 4
    for (int k = 0; k < 128; k++) s += shg[k] * W1[k*EMB + c];
    shid[c] = fmaxf(s, 0.f);
    __syncthreads();
    if (c < 2) {
        float o = b2[c];
        for (int k = 0; k < 128; k++) o += shid[k] * W2[2*k + c];
        out[2*g + c] = o;
    }
}

// ----------------------------- launch sequence -------------------------------------
extern "C" void kernel_launch(void* const* d_in, const int* in_sizes, int n_in,
                              void* d_out, int out_size)
{
    const float* h_feat = (const float*)d_in[0];
    const float* pos    = (const float*)d_in[1];
    const int*   edge   = (const int*)  d_in[2];
    const float* W_emb  = (const float*)d_in[3];
    const float* b_emb  = (const float*)d_in[4];
    const float* W_msg  = (const float*)d_in[5];
    const float* b_msg  = (const float*)d_in[6];
    const float* W_pos  = (const float*)d_in[7];
    const float* b_pos  = (const float*)d_in[8];
    const float* W_upd  = (const float*)d_in[9];
    const float* b_upd  = (const float*)d_in[10];
    const float* W1     = (const float*)d_in[11];
    const float* b1     = (const float*)d_in[12];
    const float* W2     = (const float*)d_in[13];
    const float* b2     = (const float*)d_in[14];
    float* out = (float*)d_out;

    static float* posbuf[2] = {nullptr, nullptr};
    static float* hbuf[2]   = {nullptr, nullptr};
    if (!posbuf[0]) {
        cudaGetSymbolAddress((void**)&posbuf[0], g_posA);
        cudaGetSymbolAddress((void**)&posbuf[1], g_posB);
        cudaGetSymbolAddress((void**)&hbuf[0],   g_h);
        cudaGetSymbolAddress((void**)&hbuf[1],   g_h2);
    }

    k_init<<<(NTOT*EMB + 255)/256, 256>>>(h_feat, W_emb, b_emb, pos);

    for (int l = 0; l < NLAYER; l++) {
        const float* pos_in  = posbuf[l & 1];
        float*       pos_out = posbuf[(l + 1) & 1];
        const float* hin     = hbuf[l & 1];
        float*       hout    = hbuf[(l + 1) & 1];
        if (l == 0) {
            k_count<<<(EALL + 255)/256, 256>>>(edge + EALL);
            k_scan<<<1, 1024>>>();
            k_pgemm<<<1000, 128>>>(W_msg + (size_t)l*257*EMB, b_msg + l*EMB, hin);
            k_fill<<<(EALL + 255)/256, 256>>>(edge + EALL);
            k_edge_csr<<<(NTOT*32 + 255)/256, 256>>>(
                edge, pos_in, pos_out,
                W_msg + (size_t)l*257*EMB + 256*EMB,
                W_pos + l*EMB*2, b_pos + l*2);
        } else {
            k_knn<<<BG*(NG/4), 128>>>(pos_in);
            k_pgemm<<<1000, 128>>>(W_msg + (size_t)l*257*EMB, b_msg + l*EMB, hin);
            k_edge_knn<<<(NTOT*32 + 255)/256, 256>>>(
                pos_in, pos_out,
                W_msg + (size_t)l*257*EMB + 256*EMB,
                W_pos + l*EMB*2, b_pos + l*2);
        }
        k_update<<<NTOT/128, 128>>>(W_upd + (size_t)l*256*EMB, b_upd + l*EMB, hin, hout);
        k_stats_final<<<1, 128>>>();
    }
    k_final<<<BG, 128>>>(hbuf[0], W1, b1, W2, b2, out);
}

// round 14
// speedup vs baseline: 2.1419x; 1.1877x over previous
#include <cuda_runtime.h>
#include <math.h>

#define BG     64
#define NG     1000
#define NTOT   64000
#define KNN    10
#define NLAYER 4
#define EMB    128
#define EALL   (NTOT*KNN)   /* 640000 */

typedef unsigned long long u64;
typedef unsigned int u32;

// ----------------------------- scratch (device globals) -----------------------------
__device__ float g_h   [NTOT*EMB];          // h buffer 0 (ping-pong)
__device__ float g_h2  [NTOT*EMB];          // h buffer 1 (ping-pong)
__device__ float g_magg[NTOT*EMB];
__device__ float g_p1  [NTOT*EMB];          // h_norm @ Wm1 + bm (dst)
__device__ float g_p2  [NTOT*EMB];          // h_norm @ Wm2      (src)
__device__ float g_posA[NTOT*2];
__device__ float g_posB[NTOT*2];
__device__ int   g_src [EALL];
__device__ int   g_rowptr[NTOT+1];
__device__ int   g_cnt [NTOT];
__device__ int   g_fill[NTOT];
__device__ int   g_perm[EALL];
__device__ float g_colsum[EMB];
__device__ float g_sumsq;
__device__ float g_mu[EMB];
__device__ float g_inv;
__device__ unsigned int g_done = 0;

// ----------------------------- packed f32x2 helpers --------------------------------
__device__ __forceinline__ u64 pk2(float v){
    u64 r;
    asm("mov.b64 %0, {%1, %1};" : "=l"(r) : "f"(v));
    return r;
}
__device__ __forceinline__ void fma2(u64& d, u64 a, u64 b){
    asm("fma.rn.f32x2 %0, %1, %2, %3;" : "=l"(d) : "l"(a), "l"(b), "l"(d));
}
__device__ __forceinline__ void unpk2(float& lo, float& hi, u64 v){
    asm("mov.b64 {%0, %1}, %2;" : "=f"(lo), "=f"(hi) : "l"(v));
}
__device__ __forceinline__ u64 umin64(u64 a, u64 b){ return a < b ? a : b; }

// ----------------------------- init: embed + pos copy + csr zero + norm identity ---
__global__ void k_init(const float* __restrict__ hf, const float* __restrict__ We,
                       const float* __restrict__ be, const float* __restrict__ pos)
{
    int idx = blockIdx.x*blockDim.x + threadIdx.x;
    if (idx < NTOT*2) g_posA[idx] = pos[idx];
    if (idx < NTOT)   { g_cnt[idx] = 0; g_fill[idx] = 0; }
    if (idx < 128)    g_mu[idx] = 0.f;
    if (idx == 0)     g_inv = 1.f;
    if (idx >= NTOT*EMB) return;
    int n = idx >> 7, c = idx & 127;
    float s = be[c];
    #pragma unroll
    for (int k = 0; k < 5; k++) s += hf[n*5+k] * We[k*EMB+c];
    g_h[idx] = fmaxf(s, 0.f);
}

// ----------------------------- layer-0 CSR build -----------------------------------
__global__ void k_count(const int* __restrict__ dst)
{
    int e = blockIdx.x*blockDim.x + threadIdx.x;
    if (e < EALL) atomicAdd(&g_cnt[dst[e]], 1);
}
__global__ void k_scan()   // 1 block, 1024 threads
{
    __shared__ int part[1024];
    const int CH = 63;
    int t = threadIdx.x;
    int beg = t*CH, end = min(beg + CH, NTOT);
    int s = 0;
    for (int i = beg; i < end; i++) s += g_cnt[i];
    part[t] = s;
    __syncthreads();
    if (t == 0) {
        int run = 0;
        for (int i = 0; i < 1024; i++) { int v = part[i]; part[i] = run; run += v; }
    }
    __syncthreads();
    int run = part[t];
    for (int i = beg; i < end; i++) { g_rowptr[i] = run; run += g_cnt[i]; }
    if (t == 0) g_rowptr[NTOT] = EALL;
}
__global__ void k_fill(const int* __restrict__ dst)
{
    int e = blockIdx.x*blockDim.x + threadIdx.x;
    if (e >= EALL) return;
    int d = dst[e];
    int o = atomicAdd(&g_fill[d], 1);
    g_perm[g_rowptr[d] + o] = e;
}

// ----------------------------- kNN: f32 ladder + vote-skip + u64 merge -------------
__global__ void k_knn(const float* __restrict__ pos)
{
    __shared__ float2 sp[NG];
    int g  = blockIdx.x / (NG/4);
    int nb = blockIdx.x % (NG/4);
    for (int i = threadIdx.x; i < NG; i += 128)
        sp[i] = ((const float2*)pos)[g*NG + i];
    __syncthreads();

    int w = threadIdx.x >> 5, lane = threadIdx.x & 31;
    int i = nb*4 + w;
    float2 pi = sp[i];

    float kd[KNN]; int kj[KNN];
    #pragma unroll
    for (int r = 0; r < KNN; r++) { kd[r] = 3.4e38f; kj[r] = 0x7fffffff; }

    #pragma unroll 1
    for (int it = 0; it < 32; it++) {
        int j = it*32 + lane;
        float d2 = 3.4e38f;
        if (j < NG && j != i) {
            float dx = pi.x - sp[j].x, dy = pi.y - sp[j].y;
            d2 = dx*dx + dy*dy;
        }
        bool ins = d2 < kd[KNN-1];          // strict <: exact tie keeps earlier (lower-j) entry
        if (__any_sync(0xffffffffu, ins)) {
            float cd = ins ? d2 : 3.4e38f;
            int   cj = j;
            #pragma unroll
            for (int r = 0; r < KNN; r++) {
                bool  p  = cd < kd[r];
                float dn = p ? cd : kd[r];
                float dd = p ? kd[r] : cd;
                int   jn = p ? cj : kj[r];
                int   jd = p ? kj[r] : cj;
                kd[r] = dn; cd = dd;
                kj[r] = jn; cj = jd;
            }
        }
    }

    int base = (g*NG + i)*KNN;
    #pragma unroll
    for (int r = 0; r < KNN; r++) {
        u64 cur = ((u64)__float_as_uint(kd[0]) << 32) | (u32)kj[0];
        u64 m = cur;
        #pragma unroll
        for (int off = 16; off >= 1; off >>= 1)
            m = umin64(m, __shfl_xor_sync(0xffffffffu, m, off));
        if (cur == m) {      // unique (d,j) keys -> exactly one lane pops
            #pragma unroll
            for (int r2 = 0; r2 < KNN-1; r2++) { kd[r2] = kd[r2+1]; kj[r2] = kj[r2+1]; }
            kd[KNN-1] = 3.4e38f; kj[KNN-1] = 0x7fffffff;
        }
        if (lane == 0) g_src[base + r] = g*NG + (int)(u32)(m & 0xffffffffu);
    }
}

// ----------------------------- node GEMM: P1/P2 (16x8 tile, f32x2, fused norm) -----
__global__ __launch_bounds__(128) void k_pgemm(
    const float* __restrict__ Wm, const float* __restrict__ bm,
    const float* __restrict__ hin)
{
    __shared__ __align__(16) float Xs[2][8][132];
    __shared__ __align__(16) float Ws[2][8][128];
    __shared__ float sOff[128];

    int t = threadIdx.x;
    int half = blockIdx.x >= 500;
    int n0 = (blockIdx.x - half*500) * 128;
    const float* W = Wm + (half ? EMB*EMB : 0);
    float* C = half ? g_p2 : g_p1;

    if (blockIdx.x == 0) {           // zero stats for the k_update after us
        g_colsum[t] = 0.f;
        if (t == 0) g_sumsq = 0.f;
    }
    float inv = g_inv;
    sOff[t] = -g_mu[t]*inv;

    const float* xp = hin + (size_t)(n0 + t)*EMB;
    const float* wp = W + (size_t)(t>>4)*EMB + (t&15)*8;

    float4 xa = *(const float4*)(xp);
    float4 xb = *(const float4*)(xp + 4);
    float4 wa = *(const float4*)(wp);
    float4 wb = *(const float4*)(wp + 4);

    u64 acc[16][4];
    #pragma unroll
    for (int j = 0; j < 16; j++)
        #pragma unroll
        for (int i = 0; i < 4; i++) acc[j][i] = 0ULL;

    int ry = (t>>4)*16, cx = (t&15)*8;
    __syncthreads();   // sOff visible

    Xs[0][0][t] = fmaf(xa.x, inv, sOff[0]); Xs[0][1][t] = fmaf(xa.y, inv, sOff[1]);
    Xs[0][2][t] = fmaf(xa.z, inv, sOff[2]); Xs[0][3][t] = fmaf(xa.w, inv, sOff[3]);
    Xs[0][4][t] = fmaf(xb.x, inv, sOff[4]); Xs[0][5][t] = fmaf(xb.y, inv, sOff[5]);
    Xs[0][6][t] = fmaf(xb.z, inv, sOff[6]); Xs[0][7][t] = fmaf(xb.w, inv, sOff[7]);
    *(float4*)&Ws[0][t>>4][cx]     = wa;
    *(float4*)&Ws[0][t>>4][cx + 4] = wb;
    __syncthreads();

    #pragma unroll 1
    for (int c = 0; c < 16; c++) {
        int cur = c & 1;
        if (c < 15) {
            xa = *(const float4*)(xp + (c+1)*8);
            xb = *(const float4*)(xp + (c+1)*8 + 4);
            wa = *(const float4*)(wp + (size_t)(c+1)*8*EMB);
            wb = *(const float4*)(wp + (size_t)(c+1)*8*EMB + 4);
        }
        #pragma unroll
        for (int kk = 0; kk < 8; kk++) {
            float4 a0 = *(const float4*)&Xs[cur][kk][ry];
            float4 a1 = *(const float4*)&Xs[cur][kk][ry+4];
            float4 a2 = *(const float4*)&Xs[cur][kk][ry+8];
            float4 a3 = *(const float4*)&Xs[cur][kk][ry+12];
            ulonglong2 b0 = *(const ulonglong2*)&Ws[cur][kk][cx];
            ulonglong2 b1 = *(const ulonglong2*)&Ws[cur][kk][cx+4];
            float av[16] = {a0.x,a0.y,a0.z,a0.w, a1.x,a1.y,a1.z,a1.w,
                            a2.x,a2.y,a2.z,a2.w, a3.x,a3.y,a3.z,a3.w};
            #pragma unroll
            for (int j = 0; j < 16; j++) {
                u64 ap = pk2(av[j]);
                fma2(acc[j][0], ap, b0.x);
                fma2(acc[j][1], ap, b0.y);
                fma2(acc[j][2], ap, b1.x);
                fma2(acc[j][3], ap, b1.y);
            }
        }
        if (c < 15) {
            int nxt = cur ^ 1;
            int k0 = (c+1)*8;
            Xs[nxt][0][t] = fmaf(xa.x, inv, sOff[k0+0]); Xs[nxt][1][t] = fmaf(xa.y, inv, sOff[k0+1]);
            Xs[nxt][2][t] = fmaf(xa.z, inv, sOff[k0+2]); Xs[nxt][3][t] = fmaf(xa.w, inv, sOff[k0+3]);
            Xs[nxt][4][t] = fmaf(xb.x, inv, sOff[k0+4]); Xs[nxt][5][t] = fmaf(xb.y, inv, sOff[k0+5]);
            Xs[nxt][6][t] = fmaf(xb.z, inv, sOff[k0+6]); Xs[nxt][7][t] = fmaf(xb.w, inv, sOff[k0+7]);
            *(float4*)&Ws[nxt][t>>4][cx]     = wa;
            *(float4*)&Ws[nxt][t>>4][cx + 4] = wb;
            __syncthreads();
        }
    }

    float bias[8];
    #pragma unroll
    for (int i = 0; i < 8; i++) bias[i] = half ? 0.f : bm[cx + i];
    #pragma unroll
    for (int j = 0; j < 16; j++) {
        float v[8];
        #pragma unroll
        for (int p = 0; p < 4; p++) unpk2(v[2*p], v[2*p+1], acc[j][p]);
        float* o = C + (size_t)(n0 + ry + j)*EMB + cx;
        *(float4*)(o)   = make_float4(v[0]+bias[0], v[1]+bias[1], v[2]+bias[2], v[3]+bias[3]);
        *(float4*)(o+4) = make_float4(v[4]+bias[4], v[5]+bias[5], v[6]+bias[6], v[7]+bias[7]);
    }
}

// ----------------------------- edge kernel: kNN layers (deg == 10) -----------------
__global__ __launch_bounds__(256) void k_edge_knn(
    const float* __restrict__ pos_in, float* __restrict__ pos_out,
    const float* __restrict__ Wlast, const float* __restrict__ Wp,
    const float* __restrict__ bp)
{
    int warp = (blockIdx.x*blockDim.x + threadIdx.x) >> 5;
    int lane = threadIdx.x & 31;
    if (warp >= NTOT) return;
    int n = warp;

    float4 p1  = *(const float4*)(g_p1 + (size_t)n*EMB + lane*4);
    float4 wl  = *(const float4*)(Wlast + lane*4);
    float4 wpA = *(const float4*)(Wp + lane*8);
    float4 wpB = *(const float4*)(Wp + lane*8 + 4);

    float px_i = pos_in[2*n], py_i = pos_in[2*n+1];

    int jj = 0; float pjx = 0.f, pjy = 0.f;
    if (lane < KNN) {
        jj = g_src[n*KNN + lane];
        float2 pj = ((const float2*)pos_in)[jj];
        pjx = pj.x; pjy = pj.y;
    }

    float4 macc = make_float4(0.f, 0.f, 0.f, 0.f);
    float g0[KNN], g1[KNN], dxs[KNN], dys[KNN];

    #pragma unroll
    for (int k = 0; k < KNN; k++) {
        int   j  = __shfl_sync(0xffffffffu, jj,  k);
        float dx = px_i - __shfl_sync(0xffffffffu, pjx, k);
        float dy = py_i - __shfl_sync(0xffffffffu, pjy, k);
        float dist = sqrtf(dx*dx + dy*dy);
        dxs[k] = dx; dys[k] = dy;
        float4 p2 = *(const float4*)(g_p2 + (size_t)j*EMB + lane*4);
        float v0 = fmaxf(fmaf(dist, wl.x, p1.x + p2.x), 0.f);
        float v1 = fmaxf(fmaf(dist, wl.y, p1.y + p2.y), 0.f);
        float v2 = fmaxf(fmaf(dist, wl.z, p1.z + p2.z), 0.f);
        float v3 = fmaxf(fmaf(dist, wl.w, p1.w + p2.w), 0.f);
        macc.x += v0; macc.y += v1; macc.z += v2; macc.w += v3;
        g0[k] = v0*wpA.x + v1*wpA.z + v2*wpB.x + v3*wpB.z;
        g1[k] = v0*wpA.y + v1*wpA.w + v2*wpB.y + v3*wpB.w;
    }
    #pragma unroll
    for (int off = 16; off >= 1; off >>= 1) {
        #pragma unroll
        for (int k = 0; k < KNN; k++) {
            g0[k] += __shfl_xor_sync(0xffffffffu, g0[k], off);
            g1[k] += __shfl_xor_sync(0xffffffffu, g1[k], off);
        }
    }
    *(float4*)(g_magg + (size_t)n*EMB + lane*4) = macc;
    if (lane == 0) {
        float bp0 = bp[0], bp1 = bp[1];
        float paccx = 0.f, paccy = 0.f;
        #pragma unroll
        for (int k = 0; k < KNN; k++) {
            paccx = fmaf(dxs[k], fmaxf(g0[k] + bp0, 0.f), paccx);
            paccy = fmaf(dys[k], fmaxf(g1[k] + bp1, 0.f), paccy);
        }
        pos_out[2*n]   = px_i + paccx * 0.1f;
        pos_out[2*n+1] = py_i + paccy * 0.1f;
    }
}

// ----------------------------- edge kernel: layer-0 CSR ----------------------------
__global__ __launch_bounds__(256) void k_edge_csr(
    const int* __restrict__ edge0,
    const float* __restrict__ pos_in, float* __restrict__ pos_out,
    const float* __restrict__ Wlast, const float* __restrict__ Wp,
    const float* __restrict__ bp)
{
    int warp = (blockIdx.x*blockDim.x + threadIdx.x) >> 5;
    int lane = threadIdx.x & 31;
    if (warp >= NTOT) return;
    int n = warp;

    float4 p1  = *(const float4*)(g_p1 + (size_t)n*EMB + lane*4);
    float4 wl  = *(const float4*)(Wlast + lane*4);
    float4 wpA = *(const float4*)(Wp + lane*8);
    float4 wpB = *(const float4*)(Wp + lane*8 + 4);
    float bp0 = bp[0], bp1 = bp[1];

    float px_i = pos_in[2*n], py_i = pos_in[2*n+1];
    int beg = g_rowptr[n], deg = g_rowptr[n+1] - beg;

    float4 macc = make_float4(0.f, 0.f, 0.f, 0.f);
    float paccx = 0.f, paccy = 0.f;

    for (int k = 0; k < deg; k++) {
        int j = edge0[g_perm[beg + k]];
        float dx = px_i - pos_in[2*j];
        float dy = py_i - pos_in[2*j+1];
        float dist = sqrtf(dx*dx + dy*dy);
        float4 p2 = *(const float4*)(g_p2 + (size_t)j*EMB + lane*4);
        float v0 = fmaxf(fmaf(dist, wl.x, p1.x + p2.x), 0.f);
        float v1 = fmaxf(fmaf(dist, wl.y, p1.y + p2.y), 0.f);
        float v2 = fmaxf(fmaf(dist, wl.z, p1.z + p2.z), 0.f);
        float v3 = fmaxf(fmaf(dist, wl.w, p1.w + p2.w), 0.f);
        macc.x += v0; macc.y += v1; macc.z += v2; macc.w += v3;
        float g0 = v0*wpA.x + v1*wpA.z + v2*wpB.x + v3*wpB.z;
        float g1 = v0*wpA.y + v1*wpA.w + v2*wpB.y + v3*wpB.w;
        #pragma unroll
        for (int off = 16; off >= 1; off >>= 1) {
            g0 += __shfl_xor_sync(0xffffffffu, g0, off);
            g1 += __shfl_xor_sync(0xffffffffu, g1, off);
        }
        if (lane == 0) {
            paccx = fmaf(dx, fmaxf(g0 + bp0, 0.f), paccx);
            paccy = fmaf(dy, fmaxf(g1 + bp1, 0.f), paccy);
        }
    }
    *(float4*)(g_magg + (size_t)n*EMB + lane*4) = macc;
    if (lane == 0) {
        float inv = 1.f / fmaxf((float)deg, 1.f);
        pos_out[2*n]   = px_i + paccx*inv;
        pos_out[2*n+1] = py_i + paccy*inv;
    }
}

// ----------------------------- update GEMM (16x8, f32x2, fused norm + stats) -------
__global__ __launch_bounds__(128) void k_update(
    const float* __restrict__ Wu, const float* __restrict__ bu,
    const float* __restrict__ hin, float* __restrict__ hout)
{
    __shared__ __align__(16) float Xs[2][8][132];
    __shared__ __align__(16) float Ws[2][8][128];
    __shared__ float sOff[128];
    __shared__ float sCol[128];
    __shared__ float sSq;
    __shared__ unsigned int sLast;
    __shared__ float red[4];

    int t = threadIdx.x;
    int n0 = blockIdx.x * 128;

    sCol[t] = 0.f;
    if (t == 0) sSq = 0.f;
    float inv = g_inv;
    sOff[t] = -g_mu[t]*inv;

    const float* xpA = hin    + (size_t)(n0 + t)*EMB;
    const float* xpB = g_magg + (size_t)(n0 + t)*EMB;
    const float* wp  = Wu + (size_t)(t>>4)*EMB + (t&15)*8;

    float4 xa = *(const float4*)(xpA);
    float4 xb = *(const float4*)(xpA + 4);
    float4 wa = *(const float4*)(wp);
    float4 wb = *(const float4*)(wp + 4);

    u64 acc[16][4];
    #pragma unroll
    for (int j = 0; j < 16; j++)
        #pragma unroll
        for (int i = 0; i < 4; i++) acc[j][i] = 0ULL;

    int ry = (t>>4)*16, cx = (t&15)*8;
    __syncthreads();

    Xs[0][0][t] = fmaf(xa.x, inv, sOff[0]); Xs[0][1][t] = fmaf(xa.y, inv, sOff[1]);
    Xs[0][2][t] = fmaf(xa.z, inv, sOff[2]); Xs[0][3][t] = fmaf(xa.w, inv, sOff[3]);
    Xs[0][4][t] = fmaf(xb.x, inv, sOff[4]); Xs[0][5][t] = fmaf(xb.y, inv, sOff[5]);
    Xs[0][6][t] = fmaf(xb.z, inv, sOff[6]); Xs[0][7][t] = fmaf(xb.w, inv, sOff[7]);
    *(float4*)&Ws[0][t>>4][cx]     = wa;
    *(float4*)&Ws[0][t>>4][cx + 4] = wb;
    __syncthreads();

    #pragma unroll 1
    for (int c = 0; c < 32; c++) {
        int cur = c & 1;
        int k1 = (c+1)*8;
        bool nrm = (k1 < 128);
        if (c < 31) {
            const float* src = nrm ? (xpA + k1) : (xpB + (k1 - 128));
            xa = *(const float4*)(src);
            xb = *(const float4*)(src + 4);
            wa = *(const float4*)(wp + (size_t)k1*EMB);
            wb = *(const float4*)(wp + (size_t)k1*EMB + 4);
        }
        #pragma unroll
        for (int kk = 0; kk < 8; kk++) {
            float4 a0 = *(const float4*)&Xs[cur][kk][ry];
            float4 a1 = *(const float4*)&Xs[cur][kk][ry+4];
            float4 a2 = *(const float4*)&Xs[cur][kk][ry+8];
            float4 a3 = *(const float4*)&Xs[cur][kk][ry+12];
            ulonglong2 b0 = *(const ulonglong2*)&Ws[cur][kk][cx];
            ulonglong2 b1 = *(const ulonglong2*)&Ws[cur][kk][cx+4];
            float av[16] = {a0.x,a0.y,a0.z,a0.w, a1.x,a1.y,a1.z,a1.w,
                            a2.x,a2.y,a2.z,a2.w, a3.x,a3.y,a3.z,a3.w};
            #pragma unroll
            for (int j = 0; j < 16; j++) {
                u64 ap = pk2(av[j]);
                fma2(acc[j][0], ap, b0.x);
                fma2(acc[j][1], ap, b0.y);
                fma2(acc[j][2], ap, b1.x);
                fma2(acc[j][3], ap, b1.y);
            }
        }
        if (c < 31) {
            int nxt = cur ^ 1;
            float o0 = nrm ? sOff[k1+0] : 0.f, o1 = nrm ? sOff[k1+1] : 0.f;
            float o2 = nrm ? sOff[k1+2] : 0.f, o3 = nrm ? sOff[k1+3] : 0.f;
            float o4 = nrm ? sOff[k1+4] : 0.f, o5 = nrm ? sOff[k1+5] : 0.f;
            float o6 = nrm ? sOff[k1+6] : 0.f, o7 = nrm ? sOff[k1+7] : 0.f;
            float iv = nrm ? inv : 1.f;
            Xs[nxt][0][t] = fmaf(xa.x, iv, o0); Xs[nxt][1][t] = fmaf(xa.y, iv, o1);
            Xs[nxt][2][t] = fmaf(xa.z, iv, o2); Xs[nxt][3][t] = fmaf(xa.w, iv, o3);
            Xs[nxt][4][t] = fmaf(xb.x, iv, o4); Xs[nxt][5][t] = fmaf(xb.y, iv, o5);
            Xs[nxt][6][t] = fmaf(xb.z, iv, o6); Xs[nxt][7][t] = fmaf(xb.w, iv, o7);
            *(float4*)&Ws[nxt][t>>4][cx]     = wa;
            *(float4*)&Ws[nxt][t>>4][cx + 4] = wb;
            __syncthreads();
        }
    }

    float bias[8], cps[8];
    #pragma unroll
    for (int i = 0; i < 8; i++) { bias[i] = bu[cx + i]; cps[i] = 0.f; }

    float sq = 0.f;
    #pragma unroll
    for (int j = 0; j < 16; j++) {
        float v[8];
        #pragma unroll
        for (int p = 0; p < 4; p++) unpk2(v[2*p], v[2*p+1], acc[j][p]);
        #pragma unroll
        for (int i = 0; i < 8; i++) {
            v[i] = fmaxf(v[i] + bias[i], 0.f);
            sq = fmaf(v[i], v[i], sq);
            cps[i] += v[i];
        }
        float* o = hout + (size_t)(n0 + ry + j)*EMB + cx;
        *(float4*)(o)   = make_float4(v[0], v[1], v[2], v[3]);
        *(float4*)(o+4) = make_float4(v[4], v[5], v[6], v[7]);
    }
    #pragma unroll
    for (int i = 0; i < 8; i++) atomicAdd(&sCol[cx + i], cps[i]);
    #pragma unroll
    for (int off = 16; off >= 1; off >>= 1)
        sq += __shfl_xor_sync(0xffffffffu, sq, off);
    if ((t & 31) == 0) atomicAdd(&sSq, sq);
    __syncthreads();
    atomicAdd(&g_colsum[t], sCol[t]);
    if (t == 0) atomicAdd(&g_sumsq, sSq);
    __threadfence();
    __syncthreads();
    if (t == 0) sLast = (atomicAdd(&g_done, 1) == gridDim.x - 1) ? 1u : 0u;
    __syncthreads();
    if (sLast) {
        // last block finalizes pairnorm stats (replaces k_stats_final launch)
        if (t == 0) g_done = 0;
        float mu = g_colsum[t] * (1.0f/(float)NTOT);
        g_mu[t] = mu;
        float m2 = mu*mu;
        #pragma unroll
        for (int off = 16; off >= 1; off >>= 1)
            m2 += __shfl_xor_sync(0xffffffffu, m2, off);
        if ((t & 31) == 0) red[t >> 5] = m2;
        __syncthreads();
        if (t == 0) {
            float tot = red[0] + red[1] + red[2] + red[3];
            float var = (g_sumsq - (float)NTOT * tot) * (1.0f/(float)NTOT) + 1e-5f;
            g_inv = 1.0f / sqrtf(var);
        }
    }
}

// ----------------------------- readout (applies final pairnorm after pooling) ------
__global__ void k_final(const float* __restrict__ hin,
                        const float* __restrict__ W1, const float* __restrict__ b1,
                        const float* __restrict__ W2, const float* __restrict__ b2,
                        float* __restrict__ out)
{
    int g = blockIdx.x, c = threadIdx.x;
    const float* hb = hin + (size_t)g*NG*EMB;
    float m0 = -3.4e38f, m1 = -3.4e38f, m2 = -3.4e38f, m3 = -3.4e38f;
    for (int n = 0; n < NG; n += 4) {
        m0 = fmaxf(m0, hb[(n+0)*EMB + c]);
        m1 = fmaxf(m1, hb[(n+1)*EMB + c]);
        m2 = fmaxf(m2, hb[(n+2)*EMB + c]);
        m3 = fmaxf(m3, hb[(n+3)*EMB + c]);
    }
    __shared__ float shg[128], shid[128];
    shg[c] = (fmaxf(fmaxf(m0, m1), fmaxf(m2, m3)) - g_mu[c]) * g_inv;
    __syncthreads();
    float s = b1[c];
    #pragma unroll 4
    for (int k = 0; k < 128; k++) s += shg[k] * W1[k*EMB + c];
    shid[c] = fmaxf(s, 0.f);
    __syncthreads();
    if (c < 2) {
        float o = b2[c];
        for (int k = 0; k < 128; k++) o += shid[k] * W2[2*k + c];
        out[2*g + c] = o;
    }
}

// ----------------------------- launch sequence -------------------------------------
extern "C" void kernel_launch(void* const* d_in, const int* in_sizes, int n_in,
                              void* d_out, int out_size)
{
    const float* h_feat = (const float*)d_in[0];
    const float* pos    = (const float*)d_in[1];
    const int*   edge   = (const int*)  d_in[2];
    const float* W_emb  = (const float*)d_in[3];
    const float* b_emb  = (const float*)d_in[4];
    const float* W_msg  = (const float*)d_in[5];
    const float* b_msg  = (const float*)d_in[6];
    const float* W_pos  = (const float*)d_in[7];
    const float* b_pos  = (const float*)d_in[8];
    const float* W_upd  = (const float*)d_in[9];
    const float* b_upd  = (const float*)d_in[10];
    const float* W1     = (const float*)d_in[11];
    const float* b1     = (const float*)d_in[12];
    const float* W2     = (const float*)d_in[13];
    const float* b2     = (const float*)d_in[14];
    float* out = (float*)d_out;

    static float* posbuf[2] = {nullptr, nullptr};
    static float* hbuf[2]   = {nullptr, nullptr};
    if (!posbuf[0]) {
        cudaGetSymbolAddress((void**)&posbuf[0], g_posA);
        cudaGetSymbolAddress((void**)&posbuf[1], g_posB);
        cudaGetSymbolAddress((void**)&hbuf[0],   g_h);
        cudaGetSymbolAddress((void**)&hbuf[1],   g_h2);
    }

    k_init<<<(NTOT*EMB + 255)/256, 256>>>(h_feat, W_emb, b_emb, pos);

    for (int l = 0; l < NLAYER; l++) {
        const float* pos_in  = posbuf[l & 1];
        float*       pos_out = posbuf[(l + 1) & 1];
        const float* hin     = hbuf[l & 1];
        float*       hout    = hbuf[(l + 1) & 1];
        if (l == 0) {
            k_count<<<(EALL + 255)/256, 256>>>(edge + EALL);
            k_scan<<<1, 1024>>>();
            k_pgemm<<<1000, 128>>>(W_msg + (size_t)l*257*EMB, b_msg + l*EMB, hin);
            k_fill<<<(EALL + 255)/256, 256>>>(edge + EALL);
            k_edge_csr<<<(NTOT*32 + 255)/256, 256>>>(
                edge, pos_in, pos_out,
                W_msg + (size_t)l*257*EMB + 256*EMB,
                W_pos + l*EMB*2, b_pos + l*2);
        } else {
            k_knn<<<BG*(NG/4), 128>>>(pos_in);
            k_pgemm<<<1000, 128>>>(W_msg + (size_t)l*257*EMB, b_msg + l*EMB, hin);
            k_edge_knn<<<(NTOT*32 + 255)/256, 256>>>(
                pos_in, pos_out,
                W_msg + (size_t)l*257*EMB + 256*EMB,
                W_pos + l*EMB*2, b_pos + l*2);
        }
        k_update<<<NTOT/128, 128>>>(W_upd + (size_t)l*256*EMB, b_upd + l*EMB, hin, hout);
    }
    k_final<<<BG, 128>>>(hbuf[0], W1, b1, W2, b2, out);
}

// round 17
// speedup vs baseline: 2.1439x; 1.0009x over previous
#include <cuda_runtime.h>
#include <math.h>

#define BG     64
#define NG     1000
#define NTOT   64000
#define KNN    10
#define NLAYER 4
#define EMB    128
#define EALL   (NTOT*KNN)   /* 640000 */

typedef unsigned long long u64;
typedef unsigned int u32;

// ----------------------------- scratch (device globals) -----------------------------
__device__ float g_h   [NTOT*EMB];          // h buffer 0 (ping-pong)
__device__ float g_h2  [NTOT*EMB];          // h buffer 1 (ping-pong)
__device__ float g_magg[NTOT*EMB];
__device__ float g_p1  [NTOT*EMB];          // h_norm @ Wm1 + bm (dst)
__device__ float g_p2  [NTOT*EMB];          // h_norm @ Wm2      (src)
__device__ float g_posA[NTOT*2];
__device__ float g_posB[NTOT*2];
__device__ int   g_src [EALL];
__device__ int   g_rowptr[NTOT+1];
__device__ int   g_cnt [NTOT];
__device__ int   g_fill[NTOT];
__device__ int   g_perm[EALL];
__device__ float g_colsum[EMB];
__device__ float g_sumsq;
__device__ float g_mu[EMB];
__device__ float g_inv;
__device__ unsigned int g_done = 0;

// ----------------------------- packed f32x2 helpers --------------------------------
__device__ __forceinline__ u64 pk2(float v){
    u64 r;
    asm("mov.b64 %0, {%1, %1};" : "=l"(r) : "f"(v));
    return r;
}
__device__ __forceinline__ void fma2(u64& d, u64 a, u64 b){
    asm("fma.rn.f32x2 %0, %1, %2, %3;" : "=l"(d) : "l"(a), "l"(b), "l"(d));
}
__device__ __forceinline__ void unpk2(float& lo, float& hi, u64 v){
    asm("mov.b64 {%0, %1}, %2;" : "=f"(lo), "=f"(hi) : "l"(v));
}
__device__ __forceinline__ u64 umin64(u64 a, u64 b){ return a < b ? a : b; }

// ----------------------------- init: embed + pos copy + csr zero + norm identity ---
__global__ void k_init(const float* __restrict__ hf, const float* __restrict__ We,
                       const float* __restrict__ be, const float* __restrict__ pos)
{
    int idx = blockIdx.x*blockDim.x + threadIdx.x;
    if (idx < NTOT*2) g_posA[idx] = pos[idx];
    if (idx < NTOT)   { g_cnt[idx] = 0; g_fill[idx] = 0; }
    if (idx < 128)    g_mu[idx] = 0.f;
    if (idx == 0)     g_inv = 1.f;
    if (idx >= NTOT*EMB) return;
    int n = idx >> 7, c = idx & 127;
    float s = be[c];
    #pragma unroll
    for (int k = 0; k < 5; k++) s += hf[n*5+k] * We[k*EMB+c];
    g_h[idx] = fmaxf(s, 0.f);
}

// ----------------------------- layer-0 CSR build -----------------------------------
__global__ void k_count(const int* __restrict__ dst)
{
    int e = blockIdx.x*blockDim.x + threadIdx.x;
    if (e < EALL) atomicAdd(&g_cnt[dst[e]], 1);
}
__global__ void k_scan()   // 1 block, 1024 threads
{
    __shared__ int part[1024];
    const int CH = 63;
    int t = threadIdx.x;
    int beg = t*CH, end = min(beg + CH, NTOT);
    int s = 0;
    for (int i = beg; i < end; i++) s += g_cnt[i];
    part[t] = s;
    __syncthreads();
    if (t == 0) {
        int run = 0;
        for (int i = 0; i < 1024; i++) { int v = part[i]; part[i] = run; run += v; }
    }
    __syncthreads();
    int run = part[t];
    for (int i = beg; i < end; i++) { g_rowptr[i] = run; run += g_cnt[i]; }
    if (t == 0) g_rowptr[NTOT] = EALL;
}
__global__ void k_fill(const int* __restrict__ dst)
{
    int e = blockIdx.x*blockDim.x + threadIdx.x;
    if (e >= EALL) return;
    int d = dst[e];
    int o = atomicAdd(&g_fill[d], 1);
    g_perm[g_rowptr[d] + o] = e;
}

// ----------------------------- kNN: f32 ladder + vote-skip + u64 merge -------------
__global__ void k_knn(const float* __restrict__ pos)
{
    __shared__ float2 sp[NG];
    int g  = blockIdx.x / (NG/4);
    int nb = blockIdx.x % (NG/4);
    for (int i = threadIdx.x; i < NG; i += 128)
        sp[i] = ((const float2*)pos)[g*NG + i];
    __syncthreads();

    int w = threadIdx.x >> 5, lane = threadIdx.x & 31;
    int i = nb*4 + w;
    float2 pi = sp[i];

    float kd[KNN]; int kj[KNN];
    #pragma unroll
    for (int r = 0; r < KNN; r++) { kd[r] = 3.4e38f; kj[r] = 0x7fffffff; }

    #pragma unroll 1
    for (int it = 0; it < 32; it++) {
        int j = it*32 + lane;
        float d2 = 3.4e38f;
        if (j < NG && j != i) {
            float dx = pi.x - sp[j].x, dy = pi.y - sp[j].y;
            d2 = dx*dx + dy*dy;
        }
        bool ins = d2 < kd[KNN-1];          // strict <: exact tie keeps earlier (lower-j) entry
        if (__any_sync(0xffffffffu, ins)) {
            float cd = ins ? d2 : 3.4e38f;
            int   cj = j;
            #pragma unroll
            for (int r = 0; r < KNN; r++) {
                bool  p  = cd < kd[r];
                float dn = p ? cd : kd[r];
                float dd = p ? kd[r] : cd;
                int   jn = p ? cj : kj[r];
                int   jd = p ? kj[r] : cj;
                kd[r] = dn; cd = dd;
                kj[r] = jn; cj = jd;
            }
        }
    }

    int base = (g*NG + i)*KNN;
    #pragma unroll
    for (int r = 0; r < KNN; r++) {
        u64 cur = ((u64)__float_as_uint(kd[0]) << 32) | (u32)kj[0];
        u64 m = cur;
        #pragma unroll
        for (int off = 16; off >= 1; off >>= 1)
            m = umin64(m, __shfl_xor_sync(0xffffffffu, m, off));
        if (cur == m) {      // unique (d,j) keys -> exactly one lane pops
            #pragma unroll
            for (int r2 = 0; r2 < KNN-1; r2++) { kd[r2] = kd[r2+1]; kj[r2] = kj[r2+1]; }
            kd[KNN-1] = 3.4e38f; kj[KNN-1] = 0x7fffffff;
        }
        if (lane == 0) g_src[base + r] = g*NG + (int)(u32)(m & 0xffffffffu);
    }
}

// ----------------------------- node GEMM: P1/P2 (16x8 tile, f32x2, fused norm) -----
__global__ __launch_bounds__(128) void k_pgemm(
    const float* __restrict__ Wm, const float* __restrict__ bm,
    const float* __restrict__ hin)
{
    __shared__ __align__(16) float Xs[2][8][132];
    __shared__ __align__(16) float Ws[2][8][128];
    __shared__ float sOff[128];

    int t = threadIdx.x;
    int half = blockIdx.x >= 500;
    int n0 = (blockIdx.x - half*500) * 128;
    const float* W = Wm + (half ? EMB*EMB : 0);
    float* C = half ? g_p2 : g_p1;

    if (blockIdx.x == 0) {           // zero stats for the k_update after us
        g_colsum[t] = 0.f;
        if (t == 0) g_sumsq = 0.f;
    }
    float inv = g_inv;
    sOff[t] = -g_mu[t]*inv;

    const float* xp = hin + (size_t)(n0 + t)*EMB;
    const float* wp = W + (size_t)(t>>4)*EMB + (t&15)*8;

    float4 xa = *(const float4*)(xp);
    float4 xb = *(const float4*)(xp + 4);
    float4 wa = *(const float4*)(wp);
    float4 wb = *(const float4*)(wp + 4);

    u64 acc[16][4];
    #pragma unroll
    for (int j = 0; j < 16; j++)
        #pragma unroll
        for (int i = 0; i < 4; i++) acc[j][i] = 0ULL;

    int ry = (t>>4)*16, cx = (t&15)*8;
    __syncthreads();   // sOff visible

    Xs[0][0][t] = fmaf(xa.x, inv, sOff[0]); Xs[0][1][t] = fmaf(xa.y, inv, sOff[1]);
    Xs[0][2][t] = fmaf(xa.z, inv, sOff[2]); Xs[0][3][t] = fmaf(xa.w, inv, sOff[3]);
    Xs[0][4][t] = fmaf(xb.x, inv, sOff[4]); Xs[0][5][t] = fmaf(xb.y, inv, sOff[5]);
    Xs[0][6][t] = fmaf(xb.z, inv, sOff[6]); Xs[0][7][t] = fmaf(xb.w, inv, sOff[7]);
    *(float4*)&Ws[0][t>>4][cx]     = wa;
    *(float4*)&Ws[0][t>>4][cx + 4] = wb;
    __syncthreads();

    #pragma unroll 1
    for (int c = 0; c < 16; c++) {
        int cur = c & 1;
        if (c < 15) {
            xa = *(const float4*)(xp + (c+1)*8);
            xb = *(const float4*)(xp + (c+1)*8 + 4);
            wa = *(const float4*)(wp + (size_t)(c+1)*8*EMB);
            wb = *(const float4*)(wp + (size_t)(c+1)*8*EMB + 4);
        }
        #pragma unroll
        for (int kk = 0; kk < 8; kk++) {
            float4 a0 = *(const float4*)&Xs[cur][kk][ry];
            float4 a1 = *(const float4*)&Xs[cur][kk][ry+4];
            float4 a2 = *(const float4*)&Xs[cur][kk][ry+8];
            float4 a3 = *(const float4*)&Xs[cur][kk][ry+12];
            ulonglong2 b0 = *(const ulonglong2*)&Ws[cur][kk][cx];
            ulonglong2 b1 = *(const ulonglong2*)&Ws[cur][kk][cx+4];
            float av[16] = {a0.x,a0.y,a0.z,a0.w, a1.x,a1.y,a1.z,a1.w,
                            a2.x,a2.y,a2.z,a2.w, a3.x,a3.y,a3.z,a3.w};
            #pragma unroll
            for (int j = 0; j < 16; j++) {
                u64 ap = pk2(av[j]);
                fma2(acc[j][0], ap, b0.x);
                fma2(acc[j][1], ap, b0.y);
                fma2(acc[j][2], ap, b1.x);
                fma2(acc[j][3], ap, b1.y);
            }
        }
        if (c < 15) {
            int nxt = cur ^ 1;
            int k0 = (c+1)*8;
            Xs[nxt][0][t] = fmaf(xa.x, inv, sOff[k0+0]); Xs[nxt][1][t] = fmaf(xa.y, inv, sOff[k0+1]);
            Xs[nxt][2][t] = fmaf(xa.z, inv, sOff[k0+2]); Xs[nxt][3][t] = fmaf(xa.w, inv, sOff[k0+3]);
            Xs[nxt][4][t] = fmaf(xb.x, inv, sOff[k0+4]); Xs[nxt][5][t] = fmaf(xb.y, inv, sOff[k0+5]);
            Xs[nxt][6][t] = fmaf(xb.z, inv, sOff[k0+6]); Xs[nxt][7][t] = fmaf(xb.w, inv, sOff[k0+7]);
            *(float4*)&Ws[nxt][t>>4][cx]     = wa;
            *(float4*)&Ws[nxt][t>>4][cx + 4] = wb;
            __syncthreads();
        }
    }

    float bias[8];
    #pragma unroll
    for (int i = 0; i < 8; i++) bias[i] = half ? 0.f : bm[cx + i];
    #pragma unroll
    for (int j = 0; j < 16; j++) {
        float v[8];
        #pragma unroll
        for (int p = 0; p < 4; p++) unpk2(v[2*p], v[2*p+1], acc[j][p]);
        float* o = C + (size_t)(n0 + ry + j)*EMB + cx;
        *(float4*)(o)   = make_float4(v[0]+bias[0], v[1]+bias[1], v[2]+bias[2], v[3]+bias[3]);
        *(float4*)(o+4) = make_float4(v[4]+bias[4], v[5]+bias[5], v[6]+bias[6], v[7]+bias[7]);
    }
}

// ----------------------------- edge kernel: kNN layers (deg == 10) -----------------
__global__ __launch_bounds__(256) void k_edge_knn(
    const float* __restrict__ pos_in, float* __restrict__ pos_out,
    const float* __restrict__ Wlast, const float* __restrict__ Wp,
    const float* __restrict__ bp)
{
    int warp = (blockIdx.x*blockDim.x + threadIdx.x) >> 5;
    int lane = threadIdx.x & 31;
    if (warp >= NTOT) return;
    int n = warp;

    float4 p1  = *(const float4*)(g_p1 + (size_t)n*EMB + lane*4);
    float4 wl  = *(const float4*)(Wlast + lane*4);
    float4 wpA = *(const float4*)(Wp + lane*8);
    float4 wpB = *(const float4*)(Wp + lane*8 + 4);

    float px_i = pos_in[2*n], py_i = pos_in[2*n+1];

    int jj = 0; float pjx = 0.f, pjy = 0.f;
    if (lane < KNN) {
        jj = g_src[n*KNN + lane];
        float2 pj = ((const float2*)pos_in)[jj];
        pjx = pj.x; pjy = pj.y;
    }

    float4 macc = make_float4(0.f, 0.f, 0.f, 0.f);
    float g0[KNN], g1[KNN], dxs[KNN], dys[KNN];

    #pragma unroll
    for (int k = 0; k < KNN; k++) {
        int   j  = __shfl_sync(0xffffffffu, jj,  k);
        float dx = px_i - __shfl_sync(0xffffffffu, pjx, k);
        float dy = py_i - __shfl_sync(0xffffffffu, pjy, k);
        float dist = sqrtf(dx*dx + dy*dy);
        dxs[k] = dx; dys[k] = dy;
        float4 p2 = *(const float4*)(g_p2 + (size_t)j*EMB + lane*4);
        float v0 = fmaxf(fmaf(dist, wl.x, p1.x + p2.x), 0.f);
        float v1 = fmaxf(fmaf(dist, wl.y, p1.y + p2.y), 0.f);
        float v2 = fmaxf(fmaf(dist, wl.z, p1.z + p2.z), 0.f);
        float v3 = fmaxf(fmaf(dist, wl.w, p1.w + p2.w), 0.f);
        macc.x += v0; macc.y += v1; macc.z += v2; macc.w += v3;
        g0[k] = v0*wpA.x + v1*wpA.z + v2*wpB.x + v3*wpB.z;
        g1[k] = v0*wpA.y + v1*wpA.w + v2*wpB.y + v3*wpB.w;
    }
    #pragma unroll
    for (int off = 16; off >= 1; off >>= 1) {
        #pragma unroll
        for (int k = 0; k < KNN; k++) {
            g0[k] += __shfl_xor_sync(0xffffffffu, g0[k], off);
            g1[k] += __shfl_xor_sync(0xffffffffu, g1[k], off);
        }
    }
    *(float4*)(g_magg + (size_t)n*EMB + lane*4) = macc;
    if (lane == 0) {
        float bp0 = bp[0], bp1 = bp[1];
        float paccx = 0.f, paccy = 0.f;
        #pragma unroll
        for (int k = 0; k < KNN; k++) {
            paccx = fmaf(dxs[k], fmaxf(g0[k] + bp0, 0.f), paccx);
            paccy = fmaf(dys[k], fmaxf(g1[k] + bp1, 0.f), paccy);
        }
        pos_out[2*n]   = px_i + paccx * 0.1f;
        pos_out[2*n+1] = py_i + paccy * 0.1f;
    }
}

// ----------------------------- edge kernel: layer-0 CSR ----------------------------
__global__ __launch_bounds__(256) void k_edge_csr(
    const int* __restrict__ edge0,
    const float* __restrict__ pos_in, float* __restrict__ pos_out,
    const float* __restrict__ Wlast, const float* __restrict__ Wp,
    const float* __restrict__ bp)
{
    int warp = (blockIdx.x*blockDim.x + threadIdx.x) >> 5;
    int lane = threadIdx.x & 31;
    if (warp >= NTOT) return;
    int n = warp;

    float4 p1  = *(const float4*)(g_p1 + (size_t)n*EMB + lane*4);
    float4 wl  = *(const float4*)(Wlast + lane*4);
    float4 wpA = *(const float4*)(Wp + lane*8);
    float4 wpB = *(const float4*)(Wp + lane*8 + 4);
    float bp0 = bp[0], bp1 = bp[1];

    float px_i = pos_in[2*n], py_i = pos_in[2*n+1];
    int beg = g_rowptr[n], deg = g_rowptr[n+1] - beg;

    float4 macc = make_float4(0.f, 0.f, 0.f, 0.f);
    float paccx = 0.f, paccy = 0.f;

    for (int k = 0; k < deg; k++) {
        int j = edge0[g_perm[beg + k]];
        float dx = px_i - pos_in[2*j];
        float dy = py_i - pos_in[2*j+1];
        float dist = sqrtf(dx*dx + dy*dy);
        float4 p2 = *(const float4*)(g_p2 + (size_t)j*EMB + lane*4);
        float v0 = fmaxf(fmaf(dist, wl.x, p1.x + p2.x), 0.f);
        float v1 = fmaxf(fmaf(dist, wl.y, p1.y + p2.y), 0.f);
        float v2 = fmaxf(fmaf(dist, wl.z, p1.z + p2.z), 0.f);
        float v3 = fmaxf(fmaf(dist, wl.w, p1.w + p2.w), 0.f);
        macc.x += v0; macc.y += v1; macc.z += v2; macc.w += v3;
        float g0 = v0*wpA.x + v1*wpA.z + v2*wpB.x + v3*wpB.z;
        float g1 = v0*wpA.y + v1*wpA.w + v2*wpB.y + v3*wpB.w;
        #pragma unroll
        for (int off = 16; off >= 1; off >>= 1) {
            g0 += __shfl_xor_sync(0xffffffffu, g0, off);
            g1 += __shfl_xor_sync(0xffffffffu, g1, off);
        }
        if (lane == 0) {
            paccx = fmaf(dx, fmaxf(g0 + bp0, 0.f), paccx);
            paccy = fmaf(dy, fmaxf(g1 + bp1, 0.f), paccy);
        }
    }
    *(float4*)(g_magg + (size_t)n*EMB + lane*4) = macc;
    if (lane == 0) {
        float inv = 1.f / fmaxf((float)deg, 1.f);
        pos_out[2*n]   = px_i + paccx*inv;
        pos_out[2*n+1] = py_i + paccy*inv;
    }
}

// ----------------------------- update GEMM (16x8, f32x2, fused norm + stats) -------
__global__ __launch_bounds__(128) void k_update(
    const float* __restrict__ Wu, const float* __restrict__ bu,
    const float* __restrict__ hin, float* __restrict__ hout)
{
    __shared__ __align__(16) float Xs[2][8][132];
    __shared__ __align__(16) float Ws[2][8][128];
    __shared__ float sOff[128];
    __shared__ float sCol[128];
    __shared__ float sSq;
    __shared__ unsigned int sLast;
    __shared__ float red[4];

    int t = threadIdx.x;
    int n0 = blockIdx.x * 128;

    sCol[t] = 0.f;
    if (t == 0) sSq = 0.f;
    float inv = g_inv;
    sOff[t] = -g_mu[t]*inv;

    const float* xpA = hin    + (size_t)(n0 + t)*EMB;
    const float* xpB = g_magg + (size_t)(n0 + t)*EMB;
    const float* wp  = Wu + (size_t)(t>>4)*EMB + (t&15)*8;

    float4 xa = *(const float4*)(xpA);
    float4 xb = *(const float4*)(xpA + 4);
    float4 wa = *(const float4*)(wp);
    float4 wb = *(const float4*)(wp + 4);

    u64 acc[16][4];
    #pragma unroll
    for (int j = 0; j < 16; j++)
        #pragma unroll
        for (int i = 0; i < 4; i++) acc[j][i] = 0ULL;

    int ry = (t>>4)*16, cx = (t&15)*8;
    __syncthreads();

    Xs[0][0][t] = fmaf(xa.x, inv, sOff[0]); Xs[0][1][t] = fmaf(xa.y, inv, sOff[1]);
    Xs[0][2][t] = fmaf(xa.z, inv, sOff[2]); Xs[0][3][t] = fmaf(xa.w, inv, sOff[3]);
    Xs[0][4][t] = fmaf(xb.x, inv, sOff[4]); Xs[0][5][t] = fmaf(xb.y, inv, sOff[5]);
    Xs[0][6][t] = fmaf(xb.z, inv, sOff[6]); Xs[0][7][t] = fmaf(xb.w, inv, sOff[7]);
    *(float4*)&Ws[0][t>>4][cx]     = wa;
    *(float4*)&Ws[0][t>>4][cx + 4] = wb;
    __syncthreads();

    #pragma unroll 1
    for (int c = 0; c < 32; c++) {
        int cur = c & 1;
        int k1 = (c+1)*8;
        bool nrm = (k1 < 128);
        if (c < 31) {
            const float* src = nrm ? (xpA + k1) : (xpB + (k1 - 128));
            xa = *(const float4*)(src);
            xb = *(const float4*)(src + 4);
            wa = *(const float4*)(wp + (size_t)k1*EMB);
            wb = *(const float4*)(wp + (size_t)k1*EMB + 4);
        }
        #pragma unroll
        for (int kk = 0; kk < 8; kk++) {
            float4 a0 = *(const float4*)&Xs[cur][kk][ry];
            float4 a1 = *(const float4*)&Xs[cur][kk][ry+4];
            float4 a2 = *(const float4*)&Xs[cur][kk][ry+8];
            float4 a3 = *(const float4*)&Xs[cur][kk][ry+12];
            ulonglong2 b0 = *(const ulonglong2*)&Ws[cur][kk][cx];
            ulonglong2 b1 = *(const ulonglong2*)&Ws[cur][kk][cx+4];
            float av[16] = {a0.x,a0.y,a0.z,a0.w, a1.x,a1.y,a1.z,a1.w,
                            a2.x,a2.y,a2.z,a2.w, a3.x,a3.y,a3.z,a3.w};
            #pragma unroll
            for (int j = 0; j < 16; j++) {
                u64 ap = pk2(av[j]);
                fma2(acc[j][0], ap, b0.x);
                fma2(acc[j][1], ap, b0.y);
                fma2(acc[j][2], ap, b1.x);
                fma2(acc[j][3], ap, b1.y);
            }
        }
        if (c < 31) {
            int nxt = cur ^ 1;
            float o0 = nrm ? sOff[k1+0] : 0.f, o1 = nrm ? sOff[k1+1] : 0.f;
            float o2 = nrm ? sOff[k1+2] : 0.f, o3 = nrm ? sOff[k1+3] : 0.f;
            float o4 = nrm ? sOff[k1+4] : 0.f, o5 = nrm ? sOff[k1+5] : 0.f;
            float o6 = nrm ? sOff[k1+6] : 0.f, o7 = nrm ? sOff[k1+7] : 0.f;
            float iv = nrm ? inv : 1.f;
            Xs[nxt][0][t] = fmaf(xa.x, iv, o0); Xs[nxt][1][t] = fmaf(xa.y, iv, o1);
            Xs[nxt][2][t] = fmaf(xa.z, iv, o2); Xs[nxt][3][t] = fmaf(xa.w, iv, o3);
            Xs[nxt][4][t] = fmaf(xb.x, iv, o4); Xs[nxt][5][t] = fmaf(xb.y, iv, o5);
            Xs[nxt][6][t] = fmaf(xb.z, iv, o6); Xs[nxt][7][t] = fmaf(xb.w, iv, o7);
            *(float4*)&Ws[nxt][t>>4][cx]     = wa;
            *(float4*)&Ws[nxt][t>>4][cx + 4] = wb;
            __syncthreads();
        }
    }

    float bias[8], cps[8];
    #pragma unroll
    for (int i = 0; i < 8; i++) { bias[i] = bu[cx + i]; cps[i] = 0.f; }

    float sq = 0.f;
    #pragma unroll
    for (int j = 0; j < 16; j++) {
        float v[8];
        #pragma unroll
        for (int p = 0; p < 4; p++) unpk2(v[2*p], v[2*p+1], acc[j][p]);
        #pragma unroll
        for (int i = 0; i < 8; i++) {
            v[i] = fmaxf(v[i] + bias[i], 0.f);
            sq = fmaf(v[i], v[i], sq);
            cps[i] += v[i];
        }
        float* o = hout + (size_t)(n0 + ry + j)*EMB + cx;
        *(float4*)(o)   = make_float4(v[0], v[1], v[2], v[3]);
        *(float4*)(o+4) = make_float4(v[4], v[5], v[6], v[7]);
    }
    #pragma unroll
    for (int i = 0; i < 8; i++) atomicAdd(&sCol[cx + i], cps[i]);
    #pragma unroll
    for (int off = 16; off >= 1; off >>= 1)
        sq += __shfl_xor_sync(0xffffffffu, sq, off);
    if ((t & 31) == 0) atomicAdd(&sSq, sq);
    __syncthreads();
    atomicAdd(&g_colsum[t], sCol[t]);
    if (t == 0) atomicAdd(&g_sumsq, sSq);
    __threadfence();
    __syncthreads();
    if (t == 0) sLast = (atomicAdd(&g_done, 1) == gridDim.x - 1) ? 1u : 0u;
    __syncthreads();
    if (sLast) {
        // last block finalizes pairnorm stats (replaces k_stats_final launch)
        if (t == 0) g_done = 0;
        float mu = g_colsum[t] * (1.0f/(float)NTOT);
        g_mu[t] = mu;
        float m2 = mu*mu;
        #pragma unroll
        for (int off = 16; off >= 1; off >>= 1)
            m2 += __shfl_xor_sync(0xffffffffu, m2, off);
        if ((t & 31) == 0) red[t >> 5] = m2;
        __syncthreads();
        if (t == 0) {
            float tot = red[0] + red[1] + red[2] + red[3];
            float var = (g_sumsq - (float)NTOT * tot) * (1.0f/(float)NTOT) + 1e-5f;
            g_inv = 1.0f / sqrtf(var);
        }
    }
}

// ----------------------------- readout (applies final pairnorm after pooling) ------
__global__ void k_final(const float* __restrict__ hin,
                        const float* __restrict__ W1, const float* __restrict__ b1,
                        const float* __restrict__ W2, const float* __restrict__ b2,
                        float* __restrict__ out)
{
    int g = blockIdx.x, c = threadIdx.x;
    const float* hb = hin + (size_t)g*NG*EMB;
    float m0 = -3.4e38f, m1 = -3.4e38f, m2 = -3.4e38f, m3 = -3.4e38f;
    for (int n = 0; n < NG; n += 4) {
        m0 = fmaxf(m0, hb[(n+0)*EMB + c]);
        m1 = fmaxf(m1, hb[(n+1)*EMB + c]);
        m2 = fmaxf(m2, hb[(n+2)*EMB + c]);
        m3 = fmaxf(m3, hb[(n+3)*EMB + c]);
    }
    __shared__ float shg[128], shid[128];
    shg[c] = (fmaxf(fmaxf(m0, m1), fmaxf(m2, m3)) - g_mu[c]) * g_inv;
    __syncthreads();
    float s = b1[c];
    #pragma unroll 4
    for (int k = 0; k < 128; k++) s += shg[k] * W1[k*EMB + c];
    shid[c] = fmaxf(s, 0.f);
    __syncthreads();
    if (c < 2) {
        float o = b2[c];
        for (int k = 0; k < 128; k++) o += shid[k] * W2[2*k + c];
        out[2*g + c] = o;
    }
}

// ----------------------------- launch sequence -------------------------------------
extern "C" void kernel_launch(void* const* d_in, const int* in_sizes, int n_in,
                              void* d_out, int out_size)
{
    const float* h_feat = (const float*)d_in[0];
    const float* pos    = (const float*)d_in[1];
    const int*   edge   = (const int*)  d_in[2];
    const float* W_emb  = (const float*)d_in[3];
    const float* b_emb  = (const float*)d_in[4];
    const float* W_msg  = (const float*)d_in[5];
    const float* b_msg  = (const float*)d_in[6];
    const float* W_pos  = (const float*)d_in[7];
    const float* b_pos  = (const float*)d_in[8];
    const float* W_upd  = (const float*)d_in[9];
    const float* b_upd  = (const float*)d_in[10];
    const float* W1     = (const float*)d_in[11];
    const float* b1     = (const float*)d_in[12];
    const float* W2     = (const float*)d_in[13];
    const float* b2     = (const float*)d_in[14];
    float* out = (float*)d_out;

    static float* posbuf[2] = {nullptr, nullptr};
    static float* hbuf[2]   = {nullptr, nullptr};
    if (!posbuf[0]) {
        cudaGetSymbolAddress((void**)&posbuf[0], g_posA);
        cudaGetSymbolAddress((void**)&posbuf[1], g_posB);
        cudaGetSymbolAddress((void**)&hbuf[0],   g_h);
        cudaGetSymbolAddress((void**)&hbuf[1],   g_h2);
    }

    k_init<<<(NTOT*EMB + 255)/256, 256>>>(h_feat, W_emb, b_emb, pos);

    for (int l = 0; l < NLAYER; l++) {
        const float* pos_in  = posbuf[l & 1];
        float*       pos_out = posbuf[(l + 1) & 1];
        const float* hin     = hbuf[l & 1];
        float*       hout    = hbuf[(l + 1) & 1];
        if (l == 0) {
            k_count<<<(EALL + 255)/256, 256>>>(edge + EALL);
            k_scan<<<1, 1024>>>();
            k_pgemm<<<1000, 128>>>(W_msg + (size_t)l*257*EMB, b_msg + l*EMB, hin);
            k_fill<<<(EALL + 255)/256, 256>>>(edge + EALL);
            k_edge_csr<<<(NTOT*32 + 255)/256, 256>>>(
                edge, pos_in, pos_out,
                W_msg + (size_t)l*257*EMB + 256*EMB,
                W_pos + l*EMB*2, b_pos + l*2);
        } else {
            k_knn<<<BG*(NG/4), 128>>>(pos_in);
            k_pgemm<<<1000, 128>>>(W_msg + (size_t)l*257*EMB, b_msg + l*EMB, hin);
            k_edge_knn<<<(NTOT*32 + 255)/256, 256>>>(
                pos_in, pos_out,
                W_msg + (size_t)l*257*EMB + 256*EMB,
                W_pos + l*EMB*2, b_pos + l*2);
        }
        k_update<<<NTOT/128, 128>>>(W_upd + (size_t)l*256*EMB, b_upd + l*EMB, hin, hout);
    }
    k_final<<<BG, 128>>>(hbuf[0], W1, b1, W2, b2, out);
}